// round 12
// baseline (speedup 1.0000x reference)
#include <cuda_runtime.h>
#include <math.h>

// ---------------------------------------------------------------------------
// Factorized radial-basis CNN. R12 = R11 resubmission (infra failure last
// round, theory untested):
//  - head fused into kS via last-block pattern (atomic counter, self-reset
//    for graph-replay determinism) -> one less launch + warm weight loads.
//  - kS tile load vectorized (float4).
//  - conv1 fill loop: hoisted div/mod.
//  - conv0 / conv1 mainloops: R10 byte-for-byte (best: 142.7us).
//  - hardening: counter reset via atomicExch after threadfence.
// ---------------------------------------------------------------------------

#define PZ 39
#define PX 40
#define PLANE (PZ*PZ*PX)      // 60840 floats per (b,ci) act0 plane

__device__ float g_act0[16*20*PLANE];    // zero-init => halo+pad stay 0
__device__ float g_act1[16*20*18*18*18];
__device__ float g_V[16*20*3];
__device__ unsigned int g_ctr;           // zero-init; self-reset each launch

struct BC { float b[30]; };   // [j*10 + orbit]

__host__ __device__ constexpr int orbit_of(int tz, int ty, int tx) {
    int dz = tz - 2, dy = ty - 2, dx = tx - 2;
    int r2 = dz*dz + dy*dy + dx*dx;            // {0..6, 8, 9, 12}
    return r2 <= 6 ? r2 : (r2 == 8 ? 7 : (r2 == 9 ? 8 : 9));
}

__device__ __forceinline__ void cp_async16(float* dst, const float* src) {
    unsigned int d = (unsigned int)__cvta_generic_to_shared(dst);
    asm volatile("cp.async.cg.shared.global [%0], [%1], 16;" :: "r"(d), "l"(src));
}

__device__ __forceinline__ float fast_sigmoid(float x) {
    return __fdividef(1.f, 1.f + __expf(-x));
}

// ---------------------------------------------------------------------------
// conv0: CIN=1, 64^3 -> 33^3 into padded [39,39,40]. Tile (9z,3y,33x),
// 297 threads; thread: ox=tid%33, oy=(tid/33)%3, zg=tid/99; 3 z-outputs (p).
// (R10 byte-for-byte)
// ---------------------------------------------------------------------------
__global__ void __launch_bounds__(297)
conv0_kernel(const float* __restrict__ in, const float* __restrict__ W,
             float* __restrict__ out, BC Bc)
{
    extern __shared__ float sm0[];
    float* sIn = sm0;              // 21 z x 9 y x 70 x = 13230
    float* sW  = sm0 + 13232;      // 72, 16B-aligned
    float* sB  = sW + 72;          // 30

    const int tid = threadIdx.x;
    const int b   = blockIdx.y;
    const int zt  = blockIdx.x / 11, yt = blockIdx.x % 11;
    const int oz0 = 9*zt, oy0 = 3*yt;

    if (tid < 72) { int j = tid/24, o = tid%24; sW[tid] = (o < 23) ? W[o*3 + j] : 0.f; }
    if (tid < 30) sB[tid] = Bc.b[tid];

    // ---- tile load: 630 (iy,ix) pairs, each thread sweeps z for its pairs ----
    const float* gin = in + (long)b * (64*64*64);
    {
#pragma unroll
        for (int pr = 0; pr < 3; pr++) {
            int p = tid + 297*pr;
            if (p < 630) {
                int iy = p / 70, ix = p % 70;          // once per pair
                int gy = 2*oy0 - 3 + iy;
                int gx = ix - 3;
                bool yx_ok = (ix < 69) && ((unsigned)gy < 64u) && ((unsigned)gx < 64u);
                const float* gcol = gin + ((2*oz0 - 3)*64 + gy)*64 + gx;
                float* scol = sIn + iy*70 + ix;
#pragma unroll
                for (int iz = 0; iz < 21; iz++) {
                    int gz = 2*oz0 - 3 + iz;
                    float v = 0.f;
                    if (yx_ok && (unsigned)gz < 64u)
                        v = gcol[iz*4096];
                    scol[iz*630] = v;
                }
            }
        }
    }
    __syncthreads();

    const int ox = tid % 33;
    const int r0 = tid / 33;
    const int oy = r0 % 3;
    const int zg = r0 / 3;         // 0..2; thread's z-outputs: oz0+3*zg+p

    float T[3][10];
#pragma unroll
    for (int p = 0; p < 3; p++)
#pragma unroll
        for (int g = 0; g < 10; g++) T[p][g] = 0.f;

#pragma unroll
    for (int s = 0; s < 9; s++) {          // iz = 6*zg + s ; tz = s - 2p
#pragma unroll
        for (int ty = 0; ty < 5; ty++) {
            const float2* rp = (const float2*)
                &sIn[((6*zg + s)*9 + (2*oy + ty))*70 + 2*ox];
            float2 c0 = rp[0], c1 = rp[1], c2 = rp[2];
            float v0 = c0.x, v1 = c0.y, v2 = c1.x, v3 = c1.y, v4 = c2.x;
#pragma unroll
            for (int p = 0; p < 3; p++) {
                const int tz = s - 2*p;
                if (tz >= 0 && tz <= 4) {
                    T[p][orbit_of(tz, ty, 0)] += v0;
                    T[p][orbit_of(tz, ty, 1)] += v1;
                    T[p][orbit_of(tz, ty, 2)] += v2;
                    T[p][orbit_of(tz, ty, 3)] += v3;
                    T[p][orbit_of(tz, ty, 4)] += v4;
                }
            }
        }
    }

    float U[3][3] = {};
#pragma unroll
    for (int j = 0; j < 3; j++)
#pragma unroll
    for (int g = 0; g < 10; g++) {
        float bv = sB[j*10 + g];
        U[0][j] = fmaf(bv, T[0][g], U[0][j]);
        U[1][j] = fmaf(bv, T[1][g], U[1][j]);
        U[2][j] = fmaf(bv, T[2][g], U[2][j]);
    }

    const float4* w4 = (const float4*)sW;
    float* gout = out + (long)b * 20 * PLANE
                + (oy0 + oy + 3)*PX + (ox + 3);
#pragma unroll
    for (int p = 0; p < 3; p++) {
        const int oz = oz0 + 3*zg + p;
        if (oz > 32) continue;
        float y[24];
#pragma unroll
        for (int c = 0; c < 24; c++) y[c] = 0.f;
#pragma unroll
        for (int j = 0; j < 3; j++)
#pragma unroll
        for (int q = 0; q < 6; q++) {
            float4 w = w4[j*6 + q];
            y[q*4+0] = fmaf(U[p][j], w.x, y[q*4+0]);
            y[q*4+1] = fmaf(U[p][j], w.y, y[q*4+1]);
            y[q*4+2] = fmaf(U[p][j], w.z, y[q*4+2]);
            y[q*4+3] = fmaf(U[p][j], w.w, y[q*4+3]);
        }
        float g0 = fast_sigmoid(y[20]);
        float g1 = fast_sigmoid(y[21]);
        float g2 = fast_sigmoid(y[22]);
        float* pb = gout + (long)(oz + 3)*(PZ*PX);   // channel stride = PLANE
#pragma unroll
        for (int oc = 0; oc < 20; oc++) {
            float v = (oc < 5) ? fmaxf(y[oc], 0.f)
                               : y[oc] * (oc < 8 ? g0 : (oc < 13 ? g1 : g2));
            pb[oc*PLANE] = v;
        }
    }
}

// ---------------------------------------------------------------------------
// conv1: CIN=20, act0 [39,39,40] -> 18^3. Tile (6z,6y,18x), 648 threads,
// 1 z-output/thread. Double-buffered contiguous 16B cp.async (R6 schedule).
// ---------------------------------------------------------------------------
__global__ void __launch_bounds__(648, 1)
conv1_kernel(const float* __restrict__ in, const float* __restrict__ W,
             float* __restrict__ out, BC Bc)
{
    constexpr int NT = 648, SLAB = 600;
    extern __shared__ float dsm[];
    float* buf[2] = { dsm, dsm + 9000 };
    float* sW = dsm + 18000;                  // 1440, 16B-aligned
    float* sB = sW + 1440;                    // 30

    const int tid = threadIdx.x;
    const int b   = blockIdx.y;
    const int zt  = blockIdx.x / 3, yt = blockIdx.x % 3;
    const int oz0 = 6*zt, oy0 = 6*yt;

    for (int idx = tid; idx < 1440; idx += NT) {
        int ci = idx / 72, r = idx % 72, j = r / 24, o = r % 24;
        sW[idx] = (o < 23) ? W[(o*20 + ci)*3 + j] : 0.f;
    }
    if (tid < 30) sB[tid] = Bc.b[tid];

    const int ox  = tid % 18;
    const int r0  = tid / 18;
    const int oy  = r0 % 6;
    const int ozl = r0 / 6;        // 0..5

    float acc[24];
#pragma unroll
    for (int c = 0; c < 24; c++) acc[c] = 0.f;

    // fill: thread's slab/slot fixed across iterations (div/mod hoisted)
    const int f_iz0 = tid / 150;         // first slab (tid<648 -> 0..4)
    const int f_k0  = tid % 150;
    auto issue = [&](int ci, float* dst) {
        const float* g = in + (long)(b*20 + ci)*PLANE
                            + (2*oz0)*(PZ*PX) + (2*oy0)*PX;
        int iz = f_iz0, k = f_k0;
#pragma unroll
        for (int it = 0; it < 4; it++) {      // ceil(2250/648); strided by slabs
            if (iz < 15)
                cp_async16(dst + iz*SLAB + 4*k, g + iz*(PZ*PX) + 4*k);
            iz += 4; k += 48;                  // +648 = 4 slabs + 48 slots
            if (k >= 150) { k -= 150; iz += 1; }
        }
        asm volatile("cp.async.commit_group;");
    };

    issue(0, buf[0]);
    for (int ci = 0; ci < 20; ci++) {
        float* cur = buf[ci & 1];
        if (ci + 1 < 20) {
            issue(ci + 1, buf[(ci + 1) & 1]);
            asm volatile("cp.async.wait_group 1;");
        } else {
            asm volatile("cp.async.wait_group 0;");
        }
        __syncthreads();

        float T[10];
#pragma unroll
        for (int g = 0; g < 10; g++) T[g] = 0.f;

#pragma unroll
        for (int tz = 0; tz < 5; tz++) {
#pragma unroll
            for (int ty = 0; ty < 5; ty++) {
                const float2* rp = (const float2*)
                    &cur[(2*ozl + tz)*SLAB + (2*oy + ty)*PX + 2*ox];
                float2 c0 = rp[0], c1 = rp[1], c2 = rp[2];
                T[orbit_of(tz, ty, 0)] += c0.x;
                T[orbit_of(tz, ty, 1)] += c0.y;
                T[orbit_of(tz, ty, 2)] += c1.x;
                T[orbit_of(tz, ty, 3)] += c1.y;
                T[orbit_of(tz, ty, 4)] += c2.x;
            }
        }

        float U[3] = {};
#pragma unroll
        for (int j = 0; j < 3; j++)
#pragma unroll
        for (int g = 0; g < 10; g++)
            U[j] = fmaf(sB[j*10 + g], T[g], U[j]);

        const float4* w4 = (const float4*)&sW[ci*72];
#pragma unroll
        for (int j = 0; j < 3; j++)
#pragma unroll
        for (int q = 0; q < 6; q++) {
            float4 w = w4[j*6 + q];
            acc[q*4+0] = fmaf(U[j], w.x, acc[q*4+0]);
            acc[q*4+1] = fmaf(U[j], w.y, acc[q*4+1]);
            acc[q*4+2] = fmaf(U[j], w.z, acc[q*4+2]);
            acc[q*4+3] = fmaf(U[j], w.w, acc[q*4+3]);
        }
        __syncthreads();   // protect buffer reuse
    }

    const int oz = oz0 + ozl;
    float* pb = out + (long)b * 20 * 5832
              + (long)oz*324 + (oy0 + oy)*18 + ox;      // channel stride 5832
    float g0 = fast_sigmoid(acc[20]);
    float g1 = fast_sigmoid(acc[21]);
    float g2 = fast_sigmoid(acc[22]);
#pragma unroll
    for (int oc = 0; oc < 20; oc++) {
        float y = acc[oc];
        float v = (oc < 5) ? fmaxf(y, 0.f)
                           : y * (oc < 8 ? g0 : (oc < 13 ? g1 : g2));
        pb[oc*5832] = v;
    }
}

// ---------------------------------------------------------------------------
// kS + fused B-contraction + last-block head.
//   V[b,ci,j] = sum_t B[j,orbit(t)] * S_t ; 320 blocks; the last block to
//   finish runs the FC head for all batches, then resets the counter.
// ---------------------------------------------------------------------------
__global__ void __launch_bounds__(128)
kS_head_kernel(const float* __restrict__ act, float* __restrict__ V, BC Bc,
               const float* __restrict__ W2,
               const float* __restrict__ fc1w, const float* __restrict__ fc1b,
               const float* __restrict__ fc2w, const float* __restrict__ fc2b,
               float* __restrict__ out)
{
    __shared__ float s[5832];
    __shared__ float R[1620];     // [z][y][tx]
    __shared__ float sS[128];
    __shared__ int isLast;
    int ci = blockIdx.x;
    int b  = blockIdx.y;
    int tid = threadIdx.x;        // 128
    {   // vectorized tile load
        const float4* p4 = (const float4*)(act + (long)(b*20 + ci) * 5832);
        float4* s4 = (float4*)s;
        for (int i = tid; i < 1458; i += 128) s4[i] = p4[i];
    }
    __syncthreads();

    for (int idx = tid; idx < 1620; idx += 128) {
        int z = idx / 90, r = idx % 90, y = r / 5, tx = r % 5;
        int lo = (3 - tx + 1) >> 1; if (lo < 0) lo = 0;
        int hi = (20 - tx) >> 1;    if (hi > 9) hi = 9;
        float sum = 0.f;
        const float* row = &s[(z*18 + y)*18];
        for (int oxx = lo; oxx <= hi; oxx++) sum += row[2*oxx + tx - 3];
        R[idx] = sum;
    }
    __syncthreads();

    if (tid < 125) {
        int tz = tid / 25, ty = (tid / 5) % 5, tx = tid % 5;
        int loz = (3 - tz + 1) >> 1; if (loz < 0) loz = 0;
        int hiz = (20 - tz) >> 1;    if (hiz > 9) hiz = 9;
        int loy = (3 - ty + 1) >> 1; if (loy < 0) loy = 0;
        int hiy = (20 - ty) >> 1;    if (hiy > 9) hiy = 9;
        float sum = 0.f;
        for (int oz = loz; oz <= hiz; oz++) {
            int z = 2*oz + tz - 3;
            for (int oyy = loy; oyy <= hiy; oyy++)
                sum += R[((z)*18 + (2*oyy + ty - 3))*5 + tx];
        }
        sS[tid] = sum;
    }
    __syncthreads();

    if (tid < 3) {
        float a = 0.f;
        for (int t = 0; t < 125; t++) {
            int tz = t / 25, ty = (t / 5) % 5, tx = t % 5;
            a = fmaf(Bc.b[tid*10 + orbit_of(tz, ty, tx)], sS[t], a);
        }
        V[(b*20 + ci)*3 + tid] = a;
    }

    // ---- last-block-does-head ----
    __threadfence();               // order V writes before the signal
    __syncthreads();
    if (tid == 0) {
        unsigned int v = atomicAdd(&g_ctr, 1u);
        isLast = (v == 319u) ? 1 : 0;
    }
    __syncthreads();
    if (!isLast) return;
    __threadfence();               // acquire: observe all V writes

    // reuse s[] for head staging
    float* hV  = s;                // 960
    float* hW2 = s + 960;          // 1380
    float* hF1 = s + 2340;         // 1000
    float* hP  = s + 3340;         // 320 pooled
    float* hH1 = s + 3660;         // 800
    for (int i = tid; i < 960;  i += 128) hV[i]  = V[i];
    for (int i = tid; i < 1380; i += 128) hW2[i] = W2[i];
    for (int i = tid; i < 1000; i += 128) hF1[i] = fc1w[i];
    __syncthreads();
    for (int idx = tid; idx < 320; idx += 128) {
        int bb = idx / 20, o = idx % 20;
        float a = 0.f;
        for (int k = 0; k < 60; k++)
            a = fmaf(hW2[o*60 + k], hV[bb*60 + k], a);
        hP[idx] = a * (1.0f/1000.0f);
    }
    __syncthreads();
    for (int idx = tid; idx < 800; idx += 128) {
        int bb = idx / 50, j = idx % 50;
        float a = fc1b[j];
        for (int k = 0; k < 20; k++)
            a = fmaf(hP[bb*20 + k], hF1[j*20 + k], a);
        hH1[idx] = fmaxf(a, 0.f);
    }
    __syncthreads();
    if (tid < 32) {
        int bb = tid / 2, o = tid % 2;
        float a = fc2b[o];
        for (int k = 0; k < 50; k++)
            a = fmaf(hH1[bb*50 + k], fc2w[o*50 + k], a);
        out[bb*2 + o] = a;
    }
    __threadfence();
    if (tid == 0) atomicExch(&g_ctr, 0u);   // self-reset for next replay
}

// ---------------------------------------------------------------------------
extern "C" void kernel_launch(void* const* d_in, const int* in_sizes, int n_in,
                              void* d_out, int out_size) {
    const float* inp  = (const float*)d_in[0];
    const float* W0   = (const float*)d_in[1];
    const float* W1   = (const float*)d_in[2];
    const float* W2   = (const float*)d_in[3];
    const float* fc1w = (const float*)d_in[4];
    const float* fc1b = (const float*)d_in[5];
    const float* fc2w = (const float*)d_in[6];
    const float* fc2b = (const float*)d_in[7];
    float* out = (float*)d_out;

    BC bc;
    {
        const double r2s[10]  = {0,1,2,3,4,5,6,8,9,12};
        const double mult[10] = {1,6,12,8,6,24,24,12,24,8};
        for (int j = 0; j < 3; j++) {
            double v[10], sm = 0.0;
            for (int g = 0; g < 10; g++) {
                double d = (sqrt(r2s[g]) - (double)j) / 0.6;
                v[g] = exp(-0.5 * d * d);
                sm += mult[g] * v[g] * v[g];
            }
            double inv = 1.0 / sqrt(sm);
            for (int g = 0; g < 10; g++) bc.b[j*10 + g] = (float)(v[g] * inv);
        }
    }

    float *gA0, *gA1, *gV;
    cudaGetSymbolAddress((void**)&gA0, g_act0);
    cudaGetSymbolAddress((void**)&gA1, g_act1);
    cudaGetSymbolAddress((void**)&gV,  g_V);

    constexpr int SMEM0 = (13232 + 72 + 32) * 4;        // 53.3 KB
    cudaFuncSetAttribute(conv0_kernel,
                         cudaFuncAttributeMaxDynamicSharedMemorySize, SMEM0);
    conv0_kernel<<<dim3(4*11, 16), 297, SMEM0>>>(inp, W0, gA0, bc);

    constexpr int SMEM1 = (18000 + 1440 + 32) * 4;      // 77.9 KB
    cudaFuncSetAttribute(conv1_kernel,
                         cudaFuncAttributeMaxDynamicSharedMemorySize, SMEM1);
    conv1_kernel<<<dim3(3*3, 16), 648, SMEM1>>>(gA0, W1, gA1, bc);

    kS_head_kernel<<<dim3(20, 16), 128>>>(gA1, gV, bc, W2,
                                          fc1w, fc1b, fc2w, fc2b, out);
}

// round 13
// speedup vs baseline: 1.0822x; 1.0822x over previous
#include <cuda_runtime.h>
#include <math.h>

// ---------------------------------------------------------------------------
// Factorized radial-basis CNN. R13 = R10 (best: 142.7us) with:
//  - conv0: __launch_bounds__(297,3) -> regs<=72, 3 CTAs/SM (occ fix).
//  - conv1: 3-deep cp.async ring, single barrier per ci iteration.
//  - kS / head: R10 exact (R12 fusion reverted: neutral-negative).
// ---------------------------------------------------------------------------

#define PZ 39
#define PX 40
#define PLANE (PZ*PZ*PX)      // 60840 floats per (b,ci) act0 plane

__device__ float g_act0[16*20*PLANE];    // zero-init => halo+pad stay 0
__device__ float g_act1[16*20*18*18*18];
__device__ float g_V[16*20*3];

struct BC { float b[30]; };   // [j*10 + orbit]

__host__ __device__ constexpr int orbit_of(int tz, int ty, int tx) {
    int dz = tz - 2, dy = ty - 2, dx = tx - 2;
    int r2 = dz*dz + dy*dy + dx*dx;            // {0..6, 8, 9, 12}
    return r2 <= 6 ? r2 : (r2 == 8 ? 7 : (r2 == 9 ? 8 : 9));
}

__device__ __forceinline__ void cp_async16(float* dst, const float* src) {
    unsigned int d = (unsigned int)__cvta_generic_to_shared(dst);
    asm volatile("cp.async.cg.shared.global [%0], [%1], 16;" :: "r"(d), "l"(src));
}

__device__ __forceinline__ float fast_sigmoid(float x) {
    return __fdividef(1.f, 1.f + __expf(-x));
}

// ---------------------------------------------------------------------------
// conv0: CIN=1, 64^3 -> 33^3 into padded [39,39,40]. Tile (9z,3y,33x),
// 297 threads; thread: ox=tid%33, oy=(tid/33)%3, zg=tid/99; 3 z-outputs (p).
// R10 body; 3 CTAs/SM via launch bounds.
// ---------------------------------------------------------------------------
__global__ void __launch_bounds__(297, 3)
conv0_kernel(const float* __restrict__ in, const float* __restrict__ W,
             float* __restrict__ out, BC Bc)
{
    extern __shared__ float sm0[];
    float* sIn = sm0;              // 21 z x 9 y x 70 x = 13230
    float* sW  = sm0 + 13232;      // 72, 16B-aligned
    float* sB  = sW + 72;          // 30

    const int tid = threadIdx.x;
    const int b   = blockIdx.y;
    const int zt  = blockIdx.x / 11, yt = blockIdx.x % 11;
    const int oz0 = 9*zt, oy0 = 3*yt;

    if (tid < 72) { int j = tid/24, o = tid%24; sW[tid] = (o < 23) ? W[o*3 + j] : 0.f; }
    if (tid < 30) sB[tid] = Bc.b[tid];

    // ---- tile load: 630 (iy,ix) pairs, each thread sweeps z for its pairs ----
    const float* gin = in + (long)b * (64*64*64);
    {
#pragma unroll
        for (int pr = 0; pr < 3; pr++) {
            int p = tid + 297*pr;
            if (p < 630) {
                int iy = p / 70, ix = p % 70;          // once per pair
                int gy = 2*oy0 - 3 + iy;
                int gx = ix - 3;
                bool yx_ok = (ix < 69) && ((unsigned)gy < 64u) && ((unsigned)gx < 64u);
                const float* gcol = gin + ((2*oz0 - 3)*64 + gy)*64 + gx;
                float* scol = sIn + iy*70 + ix;
#pragma unroll
                for (int iz = 0; iz < 21; iz++) {
                    int gz = 2*oz0 - 3 + iz;
                    float v = 0.f;
                    if (yx_ok && (unsigned)gz < 64u)
                        v = gcol[iz*4096];
                    scol[iz*630] = v;
                }
            }
        }
    }
    __syncthreads();

    const int ox = tid % 33;
    const int r0 = tid / 33;
    const int oy = r0 % 3;
    const int zg = r0 / 3;         // 0..2; thread's z-outputs: oz0+3*zg+p

    float T[3][10];
#pragma unroll
    for (int p = 0; p < 3; p++)
#pragma unroll
        for (int g = 0; g < 10; g++) T[p][g] = 0.f;

#pragma unroll
    for (int s = 0; s < 9; s++) {          // iz = 6*zg + s ; tz = s - 2p
#pragma unroll
        for (int ty = 0; ty < 5; ty++) {
            const float2* rp = (const float2*)
                &sIn[((6*zg + s)*9 + (2*oy + ty))*70 + 2*ox];
            float2 c0 = rp[0], c1 = rp[1], c2 = rp[2];
            float v0 = c0.x, v1 = c0.y, v2 = c1.x, v3 = c1.y, v4 = c2.x;
#pragma unroll
            for (int p = 0; p < 3; p++) {
                const int tz = s - 2*p;
                if (tz >= 0 && tz <= 4) {
                    T[p][orbit_of(tz, ty, 0)] += v0;
                    T[p][orbit_of(tz, ty, 1)] += v1;
                    T[p][orbit_of(tz, ty, 2)] += v2;
                    T[p][orbit_of(tz, ty, 3)] += v3;
                    T[p][orbit_of(tz, ty, 4)] += v4;
                }
            }
        }
    }

    float U[3][3] = {};
#pragma unroll
    for (int j = 0; j < 3; j++)
#pragma unroll
    for (int g = 0; g < 10; g++) {
        float bv = sB[j*10 + g];
        U[0][j] = fmaf(bv, T[0][g], U[0][j]);
        U[1][j] = fmaf(bv, T[1][g], U[1][j]);
        U[2][j] = fmaf(bv, T[2][g], U[2][j]);
    }

    const float4* w4 = (const float4*)sW;
    float* gout = out + (long)b * 20 * PLANE
                + (oy0 + oy + 3)*PX + (ox + 3);
#pragma unroll
    for (int p = 0; p < 3; p++) {
        const int oz = oz0 + 3*zg + p;
        if (oz > 32) continue;
        float y[24];
#pragma unroll
        for (int c = 0; c < 24; c++) y[c] = 0.f;
#pragma unroll
        for (int j = 0; j < 3; j++)
#pragma unroll
        for (int q = 0; q < 6; q++) {
            float4 w = w4[j*6 + q];
            y[q*4+0] = fmaf(U[p][j], w.x, y[q*4+0]);
            y[q*4+1] = fmaf(U[p][j], w.y, y[q*4+1]);
            y[q*4+2] = fmaf(U[p][j], w.z, y[q*4+2]);
            y[q*4+3] = fmaf(U[p][j], w.w, y[q*4+3]);
        }
        float g0 = fast_sigmoid(y[20]);
        float g1 = fast_sigmoid(y[21]);
        float g2 = fast_sigmoid(y[22]);
        float* pb = gout + (long)(oz + 3)*(PZ*PX);   // channel stride = PLANE
#pragma unroll
        for (int oc = 0; oc < 20; oc++) {
            float v = (oc < 5) ? fmaxf(y[oc], 0.f)
                               : y[oc] * (oc < 8 ? g0 : (oc < 13 ? g1 : g2));
            pb[oc*PLANE] = v;
        }
    }
}

// ---------------------------------------------------------------------------
// conv1: CIN=20, act0 [39,39,40] -> 18^3. Tile (6z,6y,18x), 648 threads,
// 1 z-output/thread. 3-deep cp.async ring -> ONE barrier per ci iteration.
// ---------------------------------------------------------------------------
__global__ void __launch_bounds__(648, 1)
conv1_kernel(const float* __restrict__ in, const float* __restrict__ W,
             float* __restrict__ out, BC Bc)
{
    constexpr int SLAB = 600;
    extern __shared__ float dsm[];
    float* bufs0 = dsm;
    float* bufs1 = dsm + 9000;
    float* bufs2 = dsm + 18000;
    float* sW = dsm + 27000;                  // 1440, 16B-aligned
    float* sB = sW + 1440;                    // 30

    const int tid = threadIdx.x;
    const int b   = blockIdx.y;
    const int zt  = blockIdx.x / 3, yt = blockIdx.x % 3;
    const int oz0 = 6*zt, oy0 = 6*yt;

    for (int idx = tid; idx < 1440; idx += 648) {
        int ci = idx / 72, r = idx % 72, j = r / 24, o = r % 24;
        sW[idx] = (o < 23) ? W[(o*20 + ci)*3 + j] : 0.f;
    }
    if (tid < 30) sB[tid] = Bc.b[tid];

    const int ox  = tid % 18;
    const int r0  = tid / 18;
    const int oy  = r0 % 6;
    const int ozl = r0 / 6;        // 0..5

    float acc[24];
#pragma unroll
    for (int c = 0; c < 24; c++) acc[c] = 0.f;

    float* bufs[3] = { bufs0, bufs1, bufs2 };

    // fill: thread's slab/slot fixed across iterations (div/mod hoisted)
    const int f_iz0 = tid / 150;
    const int f_k0  = tid % 150;
    auto issue = [&](int ci, float* dst) {
        const float* g = in + (long)(b*20 + ci)*PLANE
                            + (2*oz0)*(PZ*PX) + (2*oy0)*PX;
        int iz = f_iz0, k = f_k0;
#pragma unroll
        for (int it = 0; it < 4; it++) {
            if (iz < 15)
                cp_async16(dst + iz*SLAB + 4*k, g + iz*(PZ*PX) + 4*k);
            iz += 4; k += 48;
            if (k >= 150) { k -= 150; iz += 1; }
        }
        asm volatile("cp.async.commit_group;");
    };

    issue(0, bufs[0]);
    issue(1, bufs[1]);
    for (int ci = 0; ci < 20; ci++) {
        float* cur = bufs[ci % 3];
        if (ci < 19) { asm volatile("cp.async.wait_group 1;"); }
        else         { asm volatile("cp.async.wait_group 0;"); }
        __syncthreads();               // cur visible; fences prior reads of
                                       // bufs[(ci+2)%3] (last read at ci-1)

        float T[10];
#pragma unroll
        for (int g = 0; g < 10; g++) T[g] = 0.f;

#pragma unroll
        for (int tz = 0; tz < 5; tz++) {
#pragma unroll
            for (int ty = 0; ty < 5; ty++) {
                const float2* rp = (const float2*)
                    &cur[(2*ozl + tz)*SLAB + (2*oy + ty)*PX + 2*ox];
                float2 c0 = rp[0], c1 = rp[1], c2 = rp[2];
                T[orbit_of(tz, ty, 0)] += c0.x;
                T[orbit_of(tz, ty, 1)] += c0.y;
                T[orbit_of(tz, ty, 2)] += c1.x;
                T[orbit_of(tz, ty, 3)] += c1.y;
                T[orbit_of(tz, ty, 4)] += c2.x;
            }
        }

        float U[3] = {};
#pragma unroll
        for (int j = 0; j < 3; j++)
#pragma unroll
        for (int g = 0; g < 10; g++)
            U[j] = fmaf(sB[j*10 + g], T[g], U[j]);

        const float4* w4 = (const float4*)&sW[ci*72];
#pragma unroll
        for (int j = 0; j < 3; j++)
#pragma unroll
        for (int q = 0; q < 6; q++) {
            float4 w = w4[j*6 + q];
            acc[q*4+0] = fmaf(U[j], w.x, acc[q*4+0]);
            acc[q*4+1] = fmaf(U[j], w.y, acc[q*4+1]);
            acc[q*4+2] = fmaf(U[j], w.z, acc[q*4+2]);
            acc[q*4+3] = fmaf(U[j], w.w, acc[q*4+3]);
        }

        if (ci + 2 < 20) issue(ci + 2, bufs[(ci + 2) % 3]);
    }

    const int oz = oz0 + ozl;
    float* pb = out + (long)b * 20 * 5832
              + (long)oz*324 + (oy0 + oy)*18 + ox;      // channel stride 5832
    float g0 = fast_sigmoid(acc[20]);
    float g1 = fast_sigmoid(acc[21]);
    float g2 = fast_sigmoid(acc[22]);
#pragma unroll
    for (int oc = 0; oc < 20; oc++) {
        float y = acc[oc];
        float v = (oc < 5) ? fmaxf(y, 0.f)
                           : y * (oc < 8 ? g0 : (oc < 13 ? g1 : g2));
        pb[oc*5832] = v;
    }
}

// ---------------------------------------------------------------------------
// kS + fused B-contraction: V[b,ci,j] = sum_t B[j,orbit(t)] * S_t   (R10 exact)
// ---------------------------------------------------------------------------
__global__ void kS_kernel(const float* __restrict__ act, float* __restrict__ V,
                          BC Bc) {
    __shared__ float s[5832];
    __shared__ float R[1620];     // [z][y][tx]
    __shared__ float sS[128];
    int ci = blockIdx.x;
    int b  = blockIdx.y;
    int tid = threadIdx.x;        // 128
    {   // vectorized tile load
        const float4* p4 = (const float4*)(act + (long)(b*20 + ci) * 5832);
        float4* s4 = (float4*)s;
        for (int i = tid; i < 1458; i += 128) s4[i] = p4[i];
    }
    __syncthreads();

    for (int idx = tid; idx < 1620; idx += 128) {
        int z = idx / 90, r = idx % 90, y = r / 5, tx = r % 5;
        int lo = (3 - tx + 1) >> 1; if (lo < 0) lo = 0;
        int hi = (20 - tx) >> 1;    if (hi > 9) hi = 9;
        float sum = 0.f;
        const float* row = &s[(z*18 + y)*18];
        for (int oxx = lo; oxx <= hi; oxx++) sum += row[2*oxx + tx - 3];
        R[idx] = sum;
    }
    __syncthreads();

    if (tid < 125) {
        int tz = tid / 25, ty = (tid / 5) % 5, tx = tid % 5;
        int loz = (3 - tz + 1) >> 1; if (loz < 0) loz = 0;
        int hiz = (20 - tz) >> 1;    if (hiz > 9) hiz = 9;
        int loy = (3 - ty + 1) >> 1; if (loy < 0) loy = 0;
        int hiy = (20 - ty) >> 1;    if (hiy > 9) hiy = 9;
        float sum = 0.f;
        for (int oz = loz; oz <= hiz; oz++) {
            int z = 2*oz + tz - 3;
            for (int oyy = loy; oyy <= hiy; oyy++)
                sum += R[((z)*18 + (2*oyy + ty - 3))*5 + tx];
        }
        sS[tid] = sum;
    }
    __syncthreads();

    if (tid < 3) {
        float a = 0.f;
        for (int t = 0; t < 125; t++) {
            int tz = t / 25, ty = (t / 5) % 5, tx = t % 5;
            a = fmaf(Bc.b[tid*10 + orbit_of(tz, ty, tx)], sS[t], a);
        }
        V[(b*20 + ci)*3 + tid] = a;
    }
}

// ---------------------------------------------------------------------------
// head: one block per batch element (16 blocks x 64 threads).  (R10 exact)
// ---------------------------------------------------------------------------
__global__ void head_kernel(const float* __restrict__ V, const float* __restrict__ W2,
                            const float* __restrict__ fc1w, const float* __restrict__ fc1b,
                            const float* __restrict__ fc2w, const float* __restrict__ fc2b,
                            float* __restrict__ out)
{
    __shared__ float sV[60];
    __shared__ float sW2[1380];
    __shared__ float sF1[1000];
    __shared__ float pooled[20];
    __shared__ float h1[50];
    const int b = blockIdx.x;
    const int t = threadIdx.x;     // 64
    if (t < 60) sV[t] = V[b*60 + t];
    for (int i = t; i < 1380; i += 64) sW2[i] = W2[i];
    for (int i = t; i < 1000; i += 64) sF1[i] = fc1w[i];
    __syncthreads();
    if (t < 20) {
        float a = 0.f;
        for (int k = 0; k < 60; k++)
            a = fmaf(sW2[t*60 + k], sV[k], a);
        pooled[t] = a * (1.0f/1000.0f);
    }
    __syncthreads();
    if (t < 50) {
        float a = fc1b[t];
        for (int k = 0; k < 20; k++)
            a = fmaf(pooled[k], sF1[t*20 + k], a);
        h1[t] = fmaxf(a, 0.f);
    }
    __syncthreads();
    if (t < 2) {
        float a = fc2b[t];
        for (int k = 0; k < 50; k++)
            a = fmaf(h1[k], fc2w[t*50 + k], a);
        out[b*2 + t] = a;
    }
}

// ---------------------------------------------------------------------------
extern "C" void kernel_launch(void* const* d_in, const int* in_sizes, int n_in,
                              void* d_out, int out_size) {
    const float* inp  = (const float*)d_in[0];
    const float* W0   = (const float*)d_in[1];
    const float* W1   = (const float*)d_in[2];
    const float* W2   = (const float*)d_in[3];
    const float* fc1w = (const float*)d_in[4];
    const float* fc1b = (const float*)d_in[5];
    const float* fc2w = (const float*)d_in[6];
    const float* fc2b = (const float*)d_in[7];
    float* out = (float*)d_out;

    BC bc;
    {
        const double r2s[10]  = {0,1,2,3,4,5,6,8,9,12};
        const double mult[10] = {1,6,12,8,6,24,24,12,24,8};
        for (int j = 0; j < 3; j++) {
            double v[10], sm = 0.0;
            for (int g = 0; g < 10; g++) {
                double d = (sqrt(r2s[g]) - (double)j) / 0.6;
                v[g] = exp(-0.5 * d * d);
                sm += mult[g] * v[g] * v[g];
            }
            double inv = 1.0 / sqrt(sm);
            for (int g = 0; g < 10; g++) bc.b[j*10 + g] = (float)(v[g] * inv);
        }
    }

    float *gA0, *gA1, *gV;
    cudaGetSymbolAddress((void**)&gA0, g_act0);
    cudaGetSymbolAddress((void**)&gA1, g_act1);
    cudaGetSymbolAddress((void**)&gV,  g_V);

    constexpr int SMEM0 = (13232 + 72 + 32) * 4;        // 53.3 KB
    cudaFuncSetAttribute(conv0_kernel,
                         cudaFuncAttributeMaxDynamicSharedMemorySize, SMEM0);
    conv0_kernel<<<dim3(4*11, 16), 297, SMEM0>>>(inp, W0, gA0, bc);

    constexpr int SMEM1 = (27000 + 1440 + 32) * 4;      // 113.9 KB
    cudaFuncSetAttribute(conv1_kernel,
                         cudaFuncAttributeMaxDynamicSharedMemorySize, SMEM1);
    conv1_kernel<<<dim3(3*3, 16), 648, SMEM1>>>(gA0, W1, gA1, bc);

    kS_kernel<<<dim3(20, 16), 128>>>(gA1, gV, bc);
    head_kernel<<<16, 64>>>(gV, W2, fc1w, fc1b, fc2w, fc2b, out);
}

// round 14
// speedup vs baseline: 1.1334x; 1.0473x over previous
#include <cuda_runtime.h>
#include <math.h>

// ---------------------------------------------------------------------------
// Factorized radial-basis CNN. R14 = R13 (best: 133.1us) with:
//  - conv1: prefetch issue hoisted before compute (more overlap slack).
//  - head: 128 threads, float4 weight staging (load-latency fix).
//  - conv0 / kS: R13 byte-for-byte.
// ---------------------------------------------------------------------------

#define PZ 39
#define PX 40
#define PLANE (PZ*PZ*PX)      // 60840 floats per (b,ci) act0 plane

__device__ float g_act0[16*20*PLANE];    // zero-init => halo+pad stay 0
__device__ float g_act1[16*20*18*18*18];
__device__ float g_V[16*20*3];

struct BC { float b[30]; };   // [j*10 + orbit]

__host__ __device__ constexpr int orbit_of(int tz, int ty, int tx) {
    int dz = tz - 2, dy = ty - 2, dx = tx - 2;
    int r2 = dz*dz + dy*dy + dx*dx;            // {0..6, 8, 9, 12}
    return r2 <= 6 ? r2 : (r2 == 8 ? 7 : (r2 == 9 ? 8 : 9));
}

__device__ __forceinline__ void cp_async16(float* dst, const float* src) {
    unsigned int d = (unsigned int)__cvta_generic_to_shared(dst);
    asm volatile("cp.async.cg.shared.global [%0], [%1], 16;" :: "r"(d), "l"(src));
}

__device__ __forceinline__ float fast_sigmoid(float x) {
    return __fdividef(1.f, 1.f + __expf(-x));
}

// ---------------------------------------------------------------------------
// conv0: CIN=1, 64^3 -> 33^3 into padded [39,39,40]. Tile (9z,3y,33x),
// 297 threads; 3 CTAs/SM via launch bounds.  (R13 byte-for-byte)
// ---------------------------------------------------------------------------
__global__ void __launch_bounds__(297, 3)
conv0_kernel(const float* __restrict__ in, const float* __restrict__ W,
             float* __restrict__ out, BC Bc)
{
    extern __shared__ float sm0[];
    float* sIn = sm0;              // 21 z x 9 y x 70 x = 13230
    float* sW  = sm0 + 13232;      // 72, 16B-aligned
    float* sB  = sW + 72;          // 30

    const int tid = threadIdx.x;
    const int b   = blockIdx.y;
    const int zt  = blockIdx.x / 11, yt = blockIdx.x % 11;
    const int oz0 = 9*zt, oy0 = 3*yt;

    if (tid < 72) { int j = tid/24, o = tid%24; sW[tid] = (o < 23) ? W[o*3 + j] : 0.f; }
    if (tid < 30) sB[tid] = Bc.b[tid];

    // ---- tile load: 630 (iy,ix) pairs, each thread sweeps z for its pairs ----
    const float* gin = in + (long)b * (64*64*64);
    {
#pragma unroll
        for (int pr = 0; pr < 3; pr++) {
            int p = tid + 297*pr;
            if (p < 630) {
                int iy = p / 70, ix = p % 70;          // once per pair
                int gy = 2*oy0 - 3 + iy;
                int gx = ix - 3;
                bool yx_ok = (ix < 69) && ((unsigned)gy < 64u) && ((unsigned)gx < 64u);
                const float* gcol = gin + ((2*oz0 - 3)*64 + gy)*64 + gx;
                float* scol = sIn + iy*70 + ix;
#pragma unroll
                for (int iz = 0; iz < 21; iz++) {
                    int gz = 2*oz0 - 3 + iz;
                    float v = 0.f;
                    if (yx_ok && (unsigned)gz < 64u)
                        v = gcol[iz*4096];
                    scol[iz*630] = v;
                }
            }
        }
    }
    __syncthreads();

    const int ox = tid % 33;
    const int r0 = tid / 33;
    const int oy = r0 % 3;
    const int zg = r0 / 3;         // 0..2; thread's z-outputs: oz0+3*zg+p

    float T[3][10];
#pragma unroll
    for (int p = 0; p < 3; p++)
#pragma unroll
        for (int g = 0; g < 10; g++) T[p][g] = 0.f;

#pragma unroll
    for (int s = 0; s < 9; s++) {          // iz = 6*zg + s ; tz = s - 2p
#pragma unroll
        for (int ty = 0; ty < 5; ty++) {
            const float2* rp = (const float2*)
                &sIn[((6*zg + s)*9 + (2*oy + ty))*70 + 2*ox];
            float2 c0 = rp[0], c1 = rp[1], c2 = rp[2];
            float v0 = c0.x, v1 = c0.y, v2 = c1.x, v3 = c1.y, v4 = c2.x;
#pragma unroll
            for (int p = 0; p < 3; p++) {
                const int tz = s - 2*p;
                if (tz >= 0 && tz <= 4) {
                    T[p][orbit_of(tz, ty, 0)] += v0;
                    T[p][orbit_of(tz, ty, 1)] += v1;
                    T[p][orbit_of(tz, ty, 2)] += v2;
                    T[p][orbit_of(tz, ty, 3)] += v3;
                    T[p][orbit_of(tz, ty, 4)] += v4;
                }
            }
        }
    }

    float U[3][3] = {};
#pragma unroll
    for (int j = 0; j < 3; j++)
#pragma unroll
    for (int g = 0; g < 10; g++) {
        float bv = sB[j*10 + g];
        U[0][j] = fmaf(bv, T[0][g], U[0][j]);
        U[1][j] = fmaf(bv, T[1][g], U[1][j]);
        U[2][j] = fmaf(bv, T[2][g], U[2][j]);
    }

    const float4* w4 = (const float4*)sW;
    float* gout = out + (long)b * 20 * PLANE
                + (oy0 + oy + 3)*PX + (ox + 3);
#pragma unroll
    for (int p = 0; p < 3; p++) {
        const int oz = oz0 + 3*zg + p;
        if (oz > 32) continue;
        float y[24];
#pragma unroll
        for (int c = 0; c < 24; c++) y[c] = 0.f;
#pragma unroll
        for (int j = 0; j < 3; j++)
#pragma unroll
        for (int q = 0; q < 6; q++) {
            float4 w = w4[j*6 + q];
            y[q*4+0] = fmaf(U[p][j], w.x, y[q*4+0]);
            y[q*4+1] = fmaf(U[p][j], w.y, y[q*4+1]);
            y[q*4+2] = fmaf(U[p][j], w.z, y[q*4+2]);
            y[q*4+3] = fmaf(U[p][j], w.w, y[q*4+3]);
        }
        float g0 = fast_sigmoid(y[20]);
        float g1 = fast_sigmoid(y[21]);
        float g2 = fast_sigmoid(y[22]);
        float* pb = gout + (long)(oz + 3)*(PZ*PX);   // channel stride = PLANE
#pragma unroll
        for (int oc = 0; oc < 20; oc++) {
            float v = (oc < 5) ? fmaxf(y[oc], 0.f)
                               : y[oc] * (oc < 8 ? g0 : (oc < 13 ? g1 : g2));
            pb[oc*PLANE] = v;
        }
    }
}

// ---------------------------------------------------------------------------
// conv1: CIN=20, act0 [39,39,40] -> 18^3. Tile (6z,6y,18x), 648 threads,
// 1 z-output/thread. 3-deep cp.async ring, one barrier/iter, prefetch FIRST.
// ---------------------------------------------------------------------------
__global__ void __launch_bounds__(648, 1)
conv1_kernel(const float* __restrict__ in, const float* __restrict__ W,
             float* __restrict__ out, BC Bc)
{
    constexpr int SLAB = 600;
    extern __shared__ float dsm[];
    float* bufs0 = dsm;
    float* bufs1 = dsm + 9000;
    float* bufs2 = dsm + 18000;
    float* sW = dsm + 27000;                  // 1440, 16B-aligned
    float* sB = sW + 1440;                    // 30

    const int tid = threadIdx.x;
    const int b   = blockIdx.y;
    const int zt  = blockIdx.x / 3, yt = blockIdx.x % 3;
    const int oz0 = 6*zt, oy0 = 6*yt;

    for (int idx = tid; idx < 1440; idx += 648) {
        int ci = idx / 72, r = idx % 72, j = r / 24, o = r % 24;
        sW[idx] = (o < 23) ? W[(o*20 + ci)*3 + j] : 0.f;
    }
    if (tid < 30) sB[tid] = Bc.b[tid];

    const int ox  = tid % 18;
    const int r0  = tid / 18;
    const int oy  = r0 % 6;
    const int ozl = r0 / 6;        // 0..5

    float acc[24];
#pragma unroll
    for (int c = 0; c < 24; c++) acc[c] = 0.f;

    float* bufs[3] = { bufs0, bufs1, bufs2 };

    // fill: thread's slab/slot fixed across iterations (div/mod hoisted)
    const int f_iz0 = tid / 150;
    const int f_k0  = tid % 150;
    auto issue = [&](int ci, float* dst) {
        const float* g = in + (long)(b*20 + ci)*PLANE
                            + (2*oz0)*(PZ*PX) + (2*oy0)*PX;
        int iz = f_iz0, k = f_k0;
#pragma unroll
        for (int it = 0; it < 4; it++) {
            if (iz < 15)
                cp_async16(dst + iz*SLAB + 4*k, g + iz*(PZ*PX) + 4*k);
            iz += 4; k += 48;
            if (k >= 150) { k -= 150; iz += 1; }
        }
        asm volatile("cp.async.commit_group;");
    };

    issue(0, bufs[0]);
    issue(1, bufs[1]);
    for (int ci = 0; ci < 20; ci++) {
        float* cur = bufs[ci % 3];
        if (ci < 19) { asm volatile("cp.async.wait_group 1;"); }
        else         { asm volatile("cp.async.wait_group 0;"); }
        __syncthreads();               // cur visible; fences prior reads of
                                       // bufs[(ci+2)%3] (last read at ci-1)

        // prefetch FIRST: fill for ci+2 overlaps compute of ci and ci+1
        if (ci + 2 < 20) issue(ci + 2, bufs[(ci + 2) % 3]);

        float T[10];
#pragma unroll
        for (int g = 0; g < 10; g++) T[g] = 0.f;

#pragma unroll
        for (int tz = 0; tz < 5; tz++) {
#pragma unroll
            for (int ty = 0; ty < 5; ty++) {
                const float2* rp = (const float2*)
                    &cur[(2*ozl + tz)*SLAB + (2*oy + ty)*PX + 2*ox];
                float2 c0 = rp[0], c1 = rp[1], c2 = rp[2];
                T[orbit_of(tz, ty, 0)] += c0.x;
                T[orbit_of(tz, ty, 1)] += c0.y;
                T[orbit_of(tz, ty, 2)] += c1.x;
                T[orbit_of(tz, ty, 3)] += c1.y;
                T[orbit_of(tz, ty, 4)] += c2.x;
            }
        }

        float U[3] = {};
#pragma unroll
        for (int j = 0; j < 3; j++)
#pragma unroll
        for (int g = 0; g < 10; g++)
            U[j] = fmaf(sB[j*10 + g], T[g], U[j]);

        const float4* w4 = (const float4*)&sW[ci*72];
#pragma unroll
        for (int j = 0; j < 3; j++)
#pragma unroll
        for (int q = 0; q < 6; q++) {
            float4 w = w4[j*6 + q];
            acc[q*4+0] = fmaf(U[j], w.x, acc[q*4+0]);
            acc[q*4+1] = fmaf(U[j], w.y, acc[q*4+1]);
            acc[q*4+2] = fmaf(U[j], w.z, acc[q*4+2]);
            acc[q*4+3] = fmaf(U[j], w.w, acc[q*4+3]);
        }
    }

    const int oz = oz0 + ozl;
    float* pb = out + (long)b * 20 * 5832
              + (long)oz*324 + (oy0 + oy)*18 + ox;      // channel stride 5832
    float g0 = fast_sigmoid(acc[20]);
    float g1 = fast_sigmoid(acc[21]);
    float g2 = fast_sigmoid(acc[22]);
#pragma unroll
    for (int oc = 0; oc < 20; oc++) {
        float y = acc[oc];
        float v = (oc < 5) ? fmaxf(y, 0.f)
                           : y * (oc < 8 ? g0 : (oc < 13 ? g1 : g2));
        pb[oc*5832] = v;
    }
}

// ---------------------------------------------------------------------------
// kS + fused B-contraction: V[b,ci,j] = sum_t B[j,orbit(t)] * S_t  (R13 exact)
// ---------------------------------------------------------------------------
__global__ void kS_kernel(const float* __restrict__ act, float* __restrict__ V,
                          BC Bc) {
    __shared__ float s[5832];
    __shared__ float R[1620];     // [z][y][tx]
    __shared__ float sS[128];
    int ci = blockIdx.x;
    int b  = blockIdx.y;
    int tid = threadIdx.x;        // 128
    {   // vectorized tile load
        const float4* p4 = (const float4*)(act + (long)(b*20 + ci) * 5832);
        float4* s4 = (float4*)s;
        for (int i = tid; i < 1458; i += 128) s4[i] = p4[i];
    }
    __syncthreads();

    for (int idx = tid; idx < 1620; idx += 128) {
        int z = idx / 90, r = idx % 90, y = r / 5, tx = r % 5;
        int lo = (3 - tx + 1) >> 1; if (lo < 0) lo = 0;
        int hi = (20 - tx) >> 1;    if (hi > 9) hi = 9;
        float sum = 0.f;
        const float* row = &s[(z*18 + y)*18];
        for (int oxx = lo; oxx <= hi; oxx++) sum += row[2*oxx + tx - 3];
        R[idx] = sum;
    }
    __syncthreads();

    if (tid < 125) {
        int tz = tid / 25, ty = (tid / 5) % 5, tx = tid % 5;
        int loz = (3 - tz + 1) >> 1; if (loz < 0) loz = 0;
        int hiz = (20 - tz) >> 1;    if (hiz > 9) hiz = 9;
        int loy = (3 - ty + 1) >> 1; if (loy < 0) loy = 0;
        int hiy = (20 - ty) >> 1;    if (hiy > 9) hiy = 9;
        float sum = 0.f;
        for (int oz = loz; oz <= hiz; oz++) {
            int z = 2*oz + tz - 3;
            for (int oyy = loy; oyy <= hiy; oyy++)
                sum += R[((z)*18 + (2*oyy + ty - 3))*5 + tx];
        }
        sS[tid] = sum;
    }
    __syncthreads();

    if (tid < 3) {
        float a = 0.f;
        for (int t = 0; t < 125; t++) {
            int tz = t / 25, ty = (t / 5) % 5, tx = t % 5;
            a = fmaf(Bc.b[tid*10 + orbit_of(tz, ty, tx)], sS[t], a);
        }
        V[(b*20 + ci)*3 + tid] = a;
    }
}

// ---------------------------------------------------------------------------
// head: one block per batch element (16 blocks x 128 threads, float4 loads).
// ---------------------------------------------------------------------------
__global__ void __launch_bounds__(128)
head_kernel(const float* __restrict__ V, const float* __restrict__ W2,
            const float* __restrict__ fc1w, const float* __restrict__ fc1b,
            const float* __restrict__ fc2w, const float* __restrict__ fc2b,
            float* __restrict__ out)
{
    __shared__ float sV[60];
    __shared__ float sW2[1380];
    __shared__ float sF1[1000];
    __shared__ float pooled[20];
    __shared__ float h1[52];
    const int b = blockIdx.x;
    const int t = threadIdx.x;     // 128
    if (t < 60) sV[t] = V[b*60 + t];
    {   // float4 weight staging: 345 + 250 vec-loads across 128 threads
        const float4* w4 = (const float4*)W2;
        float4* d4 = (float4*)sW2;
        for (int i = t; i < 345; i += 128) d4[i] = w4[i];
        const float4* f4 = (const float4*)fc1w;
        float4* e4 = (float4*)sF1;
        for (int i = t; i < 250; i += 128) e4[i] = f4[i];
    }
    __syncthreads();
    if (t < 20) {
        float a = 0.f;
        for (int k = 0; k < 60; k++)
            a = fmaf(sW2[t*60 + k], sV[k], a);
        pooled[t] = a * (1.0f/1000.0f);
    }
    __syncthreads();
    if (t < 50) {
        float a = fc1b[t];
        for (int k = 0; k < 20; k++)
            a = fmaf(pooled[k], sF1[t*20 + k], a);
        h1[t] = fmaxf(a, 0.f);
    }
    __syncthreads();
    if (t < 2) {
        float a = fc2b[t];
        for (int k = 0; k < 50; k++)
            a = fmaf(h1[k], fc2w[t*50 + k], a);
        out[b*2 + t] = a;
    }
}

// ---------------------------------------------------------------------------
extern "C" void kernel_launch(void* const* d_in, const int* in_sizes, int n_in,
                              void* d_out, int out_size) {
    const float* inp  = (const float*)d_in[0];
    const float* W0   = (const float*)d_in[1];
    const float* W1   = (const float*)d_in[2];
    const float* W2   = (const float*)d_in[3];
    const float* fc1w = (const float*)d_in[4];
    const float* fc1b = (const float*)d_in[5];
    const float* fc2w = (const float*)d_in[6];
    const float* fc2b = (const float*)d_in[7];
    float* out = (float*)d_out;

    BC bc;
    {
        const double r2s[10]  = {0,1,2,3,4,5,6,8,9,12};
        const double mult[10] = {1,6,12,8,6,24,24,12,24,8};
        for (int j = 0; j < 3; j++) {
            double v[10], sm = 0.0;
            for (int g = 0; g < 10; g++) {
                double d = (sqrt(r2s[g]) - (double)j) / 0.6;
                v[g] = exp(-0.5 * d * d);
                sm += mult[g] * v[g] * v[g];
            }
            double inv = 1.0 / sqrt(sm);
            for (int g = 0; g < 10; g++) bc.b[j*10 + g] = (float)(v[g] * inv);
        }
    }

    float *gA0, *gA1, *gV;
    cudaGetSymbolAddress((void**)&gA0, g_act0);
    cudaGetSymbolAddress((void**)&gA1, g_act1);
    cudaGetSymbolAddress((void**)&gV,  g_V);

    constexpr int SMEM0 = (13232 + 72 + 32) * 4;        // 53.3 KB
    cudaFuncSetAttribute(conv0_kernel,
                         cudaFuncAttributeMaxDynamicSharedMemorySize, SMEM0);
    conv0_kernel<<<dim3(4*11, 16), 297, SMEM0>>>(inp, W0, gA0, bc);

    constexpr int SMEM1 = (27000 + 1440 + 32) * 4;      // 113.9 KB
    cudaFuncSetAttribute(conv1_kernel,
                         cudaFuncAttributeMaxDynamicSharedMemorySize, SMEM1);
    conv1_kernel<<<dim3(3*3, 16), 648, SMEM1>>>(gA0, W1, gA1, bc);

    kS_kernel<<<dim3(20, 16), 128>>>(gA1, gV, bc);
    head_kernel<<<16, 128>>>(gV, W2, fc1w, fc1b, fc2w, fc2b, out);
}

// round 15
// speedup vs baseline: 1.1409x; 1.0066x over previous
#include <cuda_runtime.h>
#include <math.h>

// ---------------------------------------------------------------------------
// Factorized radial-basis CNN. R15 = R14 (best: 127.1us) with:
//  - conv1: 6-deep cp.async ring, TWO ci per barrier phase (10 phases),
//    prefetch-first. Halves sync points; doubles per-phase ILP.
//  - conv0 / kS / head: R14 byte-for-byte.
// ---------------------------------------------------------------------------

#define PZ 39
#define PX 40
#define PLANE (PZ*PZ*PX)      // 60840 floats per (b,ci) act0 plane

__device__ float g_act0[16*20*PLANE];    // zero-init => halo+pad stay 0
__device__ float g_act1[16*20*18*18*18];
__device__ float g_V[16*20*3];

struct BC { float b[30]; };   // [j*10 + orbit]

__host__ __device__ constexpr int orbit_of(int tz, int ty, int tx) {
    int dz = tz - 2, dy = ty - 2, dx = tx - 2;
    int r2 = dz*dz + dy*dy + dx*dx;            // {0..6, 8, 9, 12}
    return r2 <= 6 ? r2 : (r2 == 8 ? 7 : (r2 == 9 ? 8 : 9));
}

__device__ __forceinline__ void cp_async16(float* dst, const float* src) {
    unsigned int d = (unsigned int)__cvta_generic_to_shared(dst);
    asm volatile("cp.async.cg.shared.global [%0], [%1], 16;" :: "r"(d), "l"(src));
}

__device__ __forceinline__ float fast_sigmoid(float x) {
    return __fdividef(1.f, 1.f + __expf(-x));
}

// ---------------------------------------------------------------------------
// conv0: CIN=1, 64^3 -> 33^3 into padded [39,39,40]. Tile (9z,3y,33x),
// 297 threads; 3 CTAs/SM via launch bounds.  (R14 byte-for-byte)
// ---------------------------------------------------------------------------
__global__ void __launch_bounds__(297, 3)
conv0_kernel(const float* __restrict__ in, const float* __restrict__ W,
             float* __restrict__ out, BC Bc)
{
    extern __shared__ float sm0[];
    float* sIn = sm0;              // 21 z x 9 y x 70 x = 13230
    float* sW  = sm0 + 13232;      // 72, 16B-aligned
    float* sB  = sW + 72;          // 30

    const int tid = threadIdx.x;
    const int b   = blockIdx.y;
    const int zt  = blockIdx.x / 11, yt = blockIdx.x % 11;
    const int oz0 = 9*zt, oy0 = 3*yt;

    if (tid < 72) { int j = tid/24, o = tid%24; sW[tid] = (o < 23) ? W[o*3 + j] : 0.f; }
    if (tid < 30) sB[tid] = Bc.b[tid];

    // ---- tile load: 630 (iy,ix) pairs, each thread sweeps z for its pairs ----
    const float* gin = in + (long)b * (64*64*64);
    {
#pragma unroll
        for (int pr = 0; pr < 3; pr++) {
            int p = tid + 297*pr;
            if (p < 630) {
                int iy = p / 70, ix = p % 70;          // once per pair
                int gy = 2*oy0 - 3 + iy;
                int gx = ix - 3;
                bool yx_ok = (ix < 69) && ((unsigned)gy < 64u) && ((unsigned)gx < 64u);
                const float* gcol = gin + ((2*oz0 - 3)*64 + gy)*64 + gx;
                float* scol = sIn + iy*70 + ix;
#pragma unroll
                for (int iz = 0; iz < 21; iz++) {
                    int gz = 2*oz0 - 3 + iz;
                    float v = 0.f;
                    if (yx_ok && (unsigned)gz < 64u)
                        v = gcol[iz*4096];
                    scol[iz*630] = v;
                }
            }
        }
    }
    __syncthreads();

    const int ox = tid % 33;
    const int r0 = tid / 33;
    const int oy = r0 % 3;
    const int zg = r0 / 3;         // 0..2; thread's z-outputs: oz0+3*zg+p

    float T[3][10];
#pragma unroll
    for (int p = 0; p < 3; p++)
#pragma unroll
        for (int g = 0; g < 10; g++) T[p][g] = 0.f;

#pragma unroll
    for (int s = 0; s < 9; s++) {          // iz = 6*zg + s ; tz = s - 2p
#pragma unroll
        for (int ty = 0; ty < 5; ty++) {
            const float2* rp = (const float2*)
                &sIn[((6*zg + s)*9 + (2*oy + ty))*70 + 2*ox];
            float2 c0 = rp[0], c1 = rp[1], c2 = rp[2];
            float v0 = c0.x, v1 = c0.y, v2 = c1.x, v3 = c1.y, v4 = c2.x;
#pragma unroll
            for (int p = 0; p < 3; p++) {
                const int tz = s - 2*p;
                if (tz >= 0 && tz <= 4) {
                    T[p][orbit_of(tz, ty, 0)] += v0;
                    T[p][orbit_of(tz, ty, 1)] += v1;
                    T[p][orbit_of(tz, ty, 2)] += v2;
                    T[p][orbit_of(tz, ty, 3)] += v3;
                    T[p][orbit_of(tz, ty, 4)] += v4;
                }
            }
        }
    }

    float U[3][3] = {};
#pragma unroll
    for (int j = 0; j < 3; j++)
#pragma unroll
    for (int g = 0; g < 10; g++) {
        float bv = sB[j*10 + g];
        U[0][j] = fmaf(bv, T[0][g], U[0][j]);
        U[1][j] = fmaf(bv, T[1][g], U[1][j]);
        U[2][j] = fmaf(bv, T[2][g], U[2][j]);
    }

    const float4* w4 = (const float4*)sW;
    float* gout = out + (long)b * 20 * PLANE
                + (oy0 + oy + 3)*PX + (ox + 3);
#pragma unroll
    for (int p = 0; p < 3; p++) {
        const int oz = oz0 + 3*zg + p;
        if (oz > 32) continue;
        float y[24];
#pragma unroll
        for (int c = 0; c < 24; c++) y[c] = 0.f;
#pragma unroll
        for (int j = 0; j < 3; j++)
#pragma unroll
        for (int q = 0; q < 6; q++) {
            float4 w = w4[j*6 + q];
            y[q*4+0] = fmaf(U[p][j], w.x, y[q*4+0]);
            y[q*4+1] = fmaf(U[p][j], w.y, y[q*4+1]);
            y[q*4+2] = fmaf(U[p][j], w.z, y[q*4+2]);
            y[q*4+3] = fmaf(U[p][j], w.w, y[q*4+3]);
        }
        float g0 = fast_sigmoid(y[20]);
        float g1 = fast_sigmoid(y[21]);
        float g2 = fast_sigmoid(y[22]);
        float* pb = gout + (long)(oz + 3)*(PZ*PX);   // channel stride = PLANE
#pragma unroll
        for (int oc = 0; oc < 20; oc++) {
            float v = (oc < 5) ? fmaxf(y[oc], 0.f)
                               : y[oc] * (oc < 8 ? g0 : (oc < 13 ? g1 : g2));
            pb[oc*PLANE] = v;
        }
    }
}

// ---------------------------------------------------------------------------
// conv1: CIN=20, act0 [39,39,40] -> 18^3. Tile (6z,6y,18x), 648 threads,
// 1 z-output/thread. 6-deep cp.async ring; 2 ci per barrier phase.
// ---------------------------------------------------------------------------
__global__ void __launch_bounds__(648, 1)
conv1_kernel(const float* __restrict__ in, const float* __restrict__ W,
             float* __restrict__ out, BC Bc)
{
    constexpr int SLAB = 600;
    extern __shared__ float dsm[];
    float* sW = dsm + 54000;                  // 1440, 16B-aligned
    float* sB = sW + 1440;                    // 30

    const int tid = threadIdx.x;
    const int b   = blockIdx.y;
    const int zt  = blockIdx.x / 3, yt = blockIdx.x % 3;
    const int oz0 = 6*zt, oy0 = 6*yt;

    for (int idx = tid; idx < 1440; idx += 648) {
        int ci = idx / 72, r = idx % 72, j = r / 24, o = r % 24;
        sW[idx] = (o < 23) ? W[(o*20 + ci)*3 + j] : 0.f;
    }
    if (tid < 30) sB[tid] = Bc.b[tid];

    const int ox  = tid % 18;
    const int r0  = tid / 18;
    const int oy  = r0 % 6;
    const int ozl = r0 / 6;        // 0..5

    float acc[24];
#pragma unroll
    for (int c = 0; c < 24; c++) acc[c] = 0.f;

    // fill: thread's slab/slot fixed across iterations (div/mod hoisted)
    const int f_iz0 = tid / 150;
    const int f_k0  = tid % 150;
    auto issue = [&](int ci) {
        float* dst = dsm + (ci % 6) * 9000;
        const float* g = in + (long)(b*20 + ci)*PLANE
                            + (2*oz0)*(PZ*PX) + (2*oy0)*PX;
        int iz = f_iz0, k = f_k0;
#pragma unroll
        for (int it = 0; it < 4; it++) {
            if (iz < 15)
                cp_async16(dst + iz*SLAB + 4*k, g + iz*(PZ*PX) + 4*k);
            iz += 4; k += 48;
            if (k >= 150) { k -= 150; iz += 1; }
        }
        asm volatile("cp.async.commit_group;");
    };

    auto compute = [&](int ci) {
        const float* cur = dsm + (ci % 6) * 9000;
        float T[10];
#pragma unroll
        for (int g = 0; g < 10; g++) T[g] = 0.f;
#pragma unroll
        for (int tz = 0; tz < 5; tz++) {
#pragma unroll
            for (int ty = 0; ty < 5; ty++) {
                const float2* rp = (const float2*)
                    &cur[(2*ozl + tz)*SLAB + (2*oy + ty)*PX + 2*ox];
                float2 c0 = rp[0], c1 = rp[1], c2 = rp[2];
                T[orbit_of(tz, ty, 0)] += c0.x;
                T[orbit_of(tz, ty, 1)] += c0.y;
                T[orbit_of(tz, ty, 2)] += c1.x;
                T[orbit_of(tz, ty, 3)] += c1.y;
                T[orbit_of(tz, ty, 4)] += c2.x;
            }
        }
        float U[3] = {};
#pragma unroll
        for (int j = 0; j < 3; j++)
#pragma unroll
        for (int g = 0; g < 10; g++)
            U[j] = fmaf(sB[j*10 + g], T[g], U[j]);
        const float4* w4 = (const float4*)&sW[ci*72];
#pragma unroll
        for (int j = 0; j < 3; j++)
#pragma unroll
        for (int q = 0; q < 6; q++) {
            float4 w = w4[j*6 + q];
            acc[q*4+0] = fmaf(U[j], w.x, acc[q*4+0]);
            acc[q*4+1] = fmaf(U[j], w.y, acc[q*4+1]);
            acc[q*4+2] = fmaf(U[j], w.z, acc[q*4+2]);
            acc[q*4+3] = fmaf(U[j], w.w, acc[q*4+3]);
        }
    };

    issue(0); issue(1); issue(2); issue(3);
    for (int cc = 0; cc < 10; cc++) {
        const int ci0 = 2*cc;
        if (cc < 9) { asm volatile("cp.async.wait_group 2;"); }
        else        { asm volatile("cp.async.wait_group 0;"); }
        __syncthreads();               // ci0, ci0+1 visible; fences prior
                                       // reads of bufs[(ci0+4)%6], [(ci0+5)%6]
                                       // (last read at phase cc-1)
        if (cc < 9) { issue(ci0 + 4); issue(ci0 + 5); }
        compute(ci0);
        compute(ci0 + 1);
    }

    const int oz = oz0 + ozl;
    float* pb = out + (long)b * 20 * 5832
              + (long)oz*324 + (oy0 + oy)*18 + ox;      // channel stride 5832
    float g0 = fast_sigmoid(acc[20]);
    float g1 = fast_sigmoid(acc[21]);
    float g2 = fast_sigmoid(acc[22]);
#pragma unroll
    for (int oc = 0; oc < 20; oc++) {
        float y = acc[oc];
        float v = (oc < 5) ? fmaxf(y, 0.f)
                           : y * (oc < 8 ? g0 : (oc < 13 ? g1 : g2));
        pb[oc*5832] = v;
    }
}

// ---------------------------------------------------------------------------
// kS + fused B-contraction: V[b,ci,j] = sum_t B[j,orbit(t)] * S_t  (R14 exact)
// ---------------------------------------------------------------------------
__global__ void kS_kernel(const float* __restrict__ act, float* __restrict__ V,
                          BC Bc) {
    __shared__ float s[5832];
    __shared__ float R[1620];     // [z][y][tx]
    __shared__ float sS[128];
    int ci = blockIdx.x;
    int b  = blockIdx.y;
    int tid = threadIdx.x;        // 128
    {   // vectorized tile load
        const float4* p4 = (const float4*)(act + (long)(b*20 + ci) * 5832);
        float4* s4 = (float4*)s;
        for (int i = tid; i < 1458; i += 128) s4[i] = p4[i];
    }
    __syncthreads();

    for (int idx = tid; idx < 1620; idx += 128) {
        int z = idx / 90, r = idx % 90, y = r / 5, tx = r % 5;
        int lo = (3 - tx + 1) >> 1; if (lo < 0) lo = 0;
        int hi = (20 - tx) >> 1;    if (hi > 9) hi = 9;
        float sum = 0.f;
        const float* row = &s[(z*18 + y)*18];
        for (int oxx = lo; oxx <= hi; oxx++) sum += row[2*oxx + tx - 3];
        R[idx] = sum;
    }
    __syncthreads();

    if (tid < 125) {
        int tz = tid / 25, ty = (tid / 5) % 5, tx = tid % 5;
        int loz = (3 - tz + 1) >> 1; if (loz < 0) loz = 0;
        int hiz = (20 - tz) >> 1;    if (hiz > 9) hiz = 9;
        int loy = (3 - ty + 1) >> 1; if (loy < 0) loy = 0;
        int hiy = (20 - ty) >> 1;    if (hiy > 9) hiy = 9;
        float sum = 0.f;
        for (int oz = loz; oz <= hiz; oz++) {
            int z = 2*oz + tz - 3;
            for (int oyy = loy; oyy <= hiy; oyy++)
                sum += R[((z)*18 + (2*oyy + ty - 3))*5 + tx];
        }
        sS[tid] = sum;
    }
    __syncthreads();

    if (tid < 3) {
        float a = 0.f;
        for (int t = 0; t < 125; t++) {
            int tz = t / 25, ty = (t / 5) % 5, tx = t % 5;
            a = fmaf(Bc.b[tid*10 + orbit_of(tz, ty, tx)], sS[t], a);
        }
        V[(b*20 + ci)*3 + tid] = a;
    }
}

// ---------------------------------------------------------------------------
// head: one block per batch element (16 blocks x 128 threads, float4 loads).
// (R14 exact)
// ---------------------------------------------------------------------------
__global__ void __launch_bounds__(128)
head_kernel(const float* __restrict__ V, const float* __restrict__ W2,
            const float* __restrict__ fc1w, const float* __restrict__ fc1b,
            const float* __restrict__ fc2w, const float* __restrict__ fc2b,
            float* __restrict__ out)
{
    __shared__ float sV[60];
    __shared__ float sW2[1380];
    __shared__ float sF1[1000];
    __shared__ float pooled[20];
    __shared__ float h1[52];
    const int b = blockIdx.x;
    const int t = threadIdx.x;     // 128
    if (t < 60) sV[t] = V[b*60 + t];
    {   // float4 weight staging: 345 + 250 vec-loads across 128 threads
        const float4* w4 = (const float4*)W2;
        float4* d4 = (float4*)sW2;
        for (int i = t; i < 345; i += 128) d4[i] = w4[i];
        const float4* f4 = (const float4*)fc1w;
        float4* e4 = (float4*)sF1;
        for (int i = t; i < 250; i += 128) e4[i] = f4[i];
    }
    __syncthreads();
    if (t < 20) {
        float a = 0.f;
        for (int k = 0; k < 60; k++)
            a = fmaf(sW2[t*60 + k], sV[k], a);
        pooled[t] = a * (1.0f/1000.0f);
    }
    __syncthreads();
    if (t < 50) {
        float a = fc1b[t];
        for (int k = 0; k < 20; k++)
            a = fmaf(pooled[k], sF1[t*20 + k], a);
        h1[t] = fmaxf(a, 0.f);
    }
    __syncthreads();
    if (t < 2) {
        float a = fc2b[t];
        for (int k = 0; k < 50; k++)
            a = fmaf(h1[k], fc2w[t*50 + k], a);
        out[b*2 + t] = a;
    }
}

// ---------------------------------------------------------------------------
extern "C" void kernel_launch(void* const* d_in, const int* in_sizes, int n_in,
                              void* d_out, int out_size) {
    const float* inp  = (const float*)d_in[0];
    const float* W0   = (const float*)d_in[1];
    const float* W1   = (const float*)d_in[2];
    const float* W2   = (const float*)d_in[3];
    const float* fc1w = (const float*)d_in[4];
    const float* fc1b = (const float*)d_in[5];
    const float* fc2w = (const float*)d_in[6];
    const float* fc2b = (const float*)d_in[7];
    float* out = (float*)d_out;

    BC bc;
    {
        const double r2s[10]  = {0,1,2,3,4,5,6,8,9,12};
        const double mult[10] = {1,6,12,8,6,24,24,12,24,8};
        for (int j = 0; j < 3; j++) {
            double v[10], sm = 0.0;
            for (int g = 0; g < 10; g++) {
                double d = (sqrt(r2s[g]) - (double)j) / 0.6;
                v[g] = exp(-0.5 * d * d);
                sm += mult[g] * v[g] * v[g];
            }
            double inv = 1.0 / sqrt(sm);
            for (int g = 0; g < 10; g++) bc.b[j*10 + g] = (float)(v[g] * inv);
        }
    }

    float *gA0, *gA1, *gV;
    cudaGetSymbolAddress((void**)&gA0, g_act0);
    cudaGetSymbolAddress((void**)&gA1, g_act1);
    cudaGetSymbolAddress((void**)&gV,  g_V);

    constexpr int SMEM0 = (13232 + 72 + 32) * 4;        // 53.3 KB
    cudaFuncSetAttribute(conv0_kernel,
                         cudaFuncAttributeMaxDynamicSharedMemorySize, SMEM0);
    conv0_kernel<<<dim3(4*11, 16), 297, SMEM0>>>(inp, W0, gA0, bc);

    constexpr int SMEM1 = (54000 + 1440 + 32) * 4;      // 221.8 KB
    cudaFuncSetAttribute(conv1_kernel,
                         cudaFuncAttributeMaxDynamicSharedMemorySize, SMEM1);
    conv1_kernel<<<dim3(3*3, 16), 648, SMEM1>>>(gA0, W1, gA1, bc);

    kS_kernel<<<dim3(20, 16), 128>>>(gA1, gV, bc);
    head_kernel<<<16, 128>>>(gV, W2, fc1w, fc1b, fc2w, fc2b, out);
}

// round 16
// speedup vs baseline: 1.1532x; 1.0108x over previous
#include <cuda_runtime.h>
#include <math.h>

// ---------------------------------------------------------------------------
// Factorized radial-basis CNN. R16 = R15 (best: 126.3us) + PDL overlap:
//  - conv1/kS/head launched with programmatic stream serialization; each
//    runs its input-independent prologue, then griddepcontrol.wait.
//  - producers call griddepcontrol.launch_dependents early (scheduling hint;
//    memory safety comes from the consumer-side wait = full-grid completion).
//  - all kernel bodies otherwise R15 byte-for-byte.
// ---------------------------------------------------------------------------

#define PZ 39
#define PX 40
#define PLANE (PZ*PZ*PX)      // 60840 floats per (b,ci) act0 plane

__device__ float g_act0[16*20*PLANE];    // zero-init => halo+pad stay 0
__device__ float g_act1[16*20*18*18*18];
__device__ float g_V[16*20*3];

struct BC { float b[30]; };   // [j*10 + orbit]

__host__ __device__ constexpr int orbit_of(int tz, int ty, int tx) {
    int dz = tz - 2, dy = ty - 2, dx = tx - 2;
    int r2 = dz*dz + dy*dy + dx*dx;            // {0..6, 8, 9, 12}
    return r2 <= 6 ? r2 : (r2 == 8 ? 7 : (r2 == 9 ? 8 : 9));
}

__device__ __forceinline__ void cp_async16(float* dst, const float* src) {
    unsigned int d = (unsigned int)__cvta_generic_to_shared(dst);
    asm volatile("cp.async.cg.shared.global [%0], [%1], 16;" :: "r"(d), "l"(src));
}

__device__ __forceinline__ float fast_sigmoid(float x) {
    return __fdividef(1.f, 1.f + __expf(-x));
}

// PDL intrinsics (sm_90+). wait = full upstream-grid completion + visibility;
// completes immediately when kernel wasn't launched as a dependent.
__device__ __forceinline__ void gdc_wait()   { asm volatile("griddepcontrol.wait;" ::: "memory"); }
__device__ __forceinline__ void gdc_launch() { asm volatile("griddepcontrol.launch_dependents;"); }

// ---------------------------------------------------------------------------
// conv0: CIN=1, 64^3 -> 33^3 into padded [39,39,40]. Tile (9z,3y,33x),
// 297 threads; 3 CTAs/SM via launch bounds.  (R15 body + early trigger)
// ---------------------------------------------------------------------------
__global__ void __launch_bounds__(297, 3)
conv0_kernel(const float* __restrict__ in, const float* __restrict__ W,
             float* __restrict__ out, BC Bc)
{
    extern __shared__ float sm0[];
    float* sIn = sm0;              // 21 z x 9 y x 70 x = 13230
    float* sW  = sm0 + 13232;      // 72, 16B-aligned
    float* sB  = sW + 72;          // 30

    const int tid = threadIdx.x;
    const int b   = blockIdx.y;
    const int zt  = blockIdx.x / 11, yt = blockIdx.x % 11;
    const int oz0 = 9*zt, oy0 = 3*yt;

    if (tid < 72) { int j = tid/24, o = tid%24; sW[tid] = (o < 23) ? W[o*3 + j] : 0.f; }
    if (tid < 30) sB[tid] = Bc.b[tid];

    // ---- tile load: 630 (iy,ix) pairs, each thread sweeps z for its pairs ----
    const float* gin = in + (long)b * (64*64*64);
    {
#pragma unroll
        for (int pr = 0; pr < 3; pr++) {
            int p = tid + 297*pr;
            if (p < 630) {
                int iy = p / 70, ix = p % 70;          // once per pair
                int gy = 2*oy0 - 3 + iy;
                int gx = ix - 3;
                bool yx_ok = (ix < 69) && ((unsigned)gy < 64u) && ((unsigned)gx < 64u);
                const float* gcol = gin + ((2*oz0 - 3)*64 + gy)*64 + gx;
                float* scol = sIn + iy*70 + ix;
#pragma unroll
                for (int iz = 0; iz < 21; iz++) {
                    int gz = 2*oz0 - 3 + iz;
                    float v = 0.f;
                    if (yx_ok && (unsigned)gz < 64u)
                        v = gcol[iz*4096];
                    scol[iz*630] = v;
                }
            }
        }
    }
    __syncthreads();
    gdc_launch();                  // all CTAs scheduled+past load -> let conv1 start

    const int ox = tid % 33;
    const int r0 = tid / 33;
    const int oy = r0 % 3;
    const int zg = r0 / 3;         // 0..2; thread's z-outputs: oz0+3*zg+p

    float T[3][10];
#pragma unroll
    for (int p = 0; p < 3; p++)
#pragma unroll
        for (int g = 0; g < 10; g++) T[p][g] = 0.f;

#pragma unroll
    for (int s = 0; s < 9; s++) {          // iz = 6*zg + s ; tz = s - 2p
#pragma unroll
        for (int ty = 0; ty < 5; ty++) {
            const float2* rp = (const float2*)
                &sIn[((6*zg + s)*9 + (2*oy + ty))*70 + 2*ox];
            float2 c0 = rp[0], c1 = rp[1], c2 = rp[2];
            float v0 = c0.x, v1 = c0.y, v2 = c1.x, v3 = c1.y, v4 = c2.x;
#pragma unroll
            for (int p = 0; p < 3; p++) {
                const int tz = s - 2*p;
                if (tz >= 0 && tz <= 4) {
                    T[p][orbit_of(tz, ty, 0)] += v0;
                    T[p][orbit_of(tz, ty, 1)] += v1;
                    T[p][orbit_of(tz, ty, 2)] += v2;
                    T[p][orbit_of(tz, ty, 3)] += v3;
                    T[p][orbit_of(tz, ty, 4)] += v4;
                }
            }
        }
    }

    float U[3][3] = {};
#pragma unroll
    for (int j = 0; j < 3; j++)
#pragma unroll
    for (int g = 0; g < 10; g++) {
        float bv = sB[j*10 + g];
        U[0][j] = fmaf(bv, T[0][g], U[0][j]);
        U[1][j] = fmaf(bv, T[1][g], U[1][j]);
        U[2][j] = fmaf(bv, T[2][g], U[2][j]);
    }

    const float4* w4 = (const float4*)sW;
    float* gout = out + (long)b * 20 * PLANE
                + (oy0 + oy + 3)*PX + (ox + 3);
#pragma unroll
    for (int p = 0; p < 3; p++) {
        const int oz = oz0 + 3*zg + p;
        if (oz > 32) continue;
        float y[24];
#pragma unroll
        for (int c = 0; c < 24; c++) y[c] = 0.f;
#pragma unroll
        for (int j = 0; j < 3; j++)
#pragma unroll
        for (int q = 0; q < 6; q++) {
            float4 w = w4[j*6 + q];
            y[q*4+0] = fmaf(U[p][j], w.x, y[q*4+0]);
            y[q*4+1] = fmaf(U[p][j], w.y, y[q*4+1]);
            y[q*4+2] = fmaf(U[p][j], w.z, y[q*4+2]);
            y[q*4+3] = fmaf(U[p][j], w.w, y[q*4+3]);
        }
        float g0 = fast_sigmoid(y[20]);
        float g1 = fast_sigmoid(y[21]);
        float g2 = fast_sigmoid(y[22]);
        float* pb = gout + (long)(oz + 3)*(PZ*PX);   // channel stride = PLANE
#pragma unroll
        for (int oc = 0; oc < 20; oc++) {
            float v = (oc < 5) ? fmaxf(y[oc], 0.f)
                               : y[oc] * (oc < 8 ? g0 : (oc < 13 ? g1 : g2));
            pb[oc*PLANE] = v;
        }
    }
}

// ---------------------------------------------------------------------------
// conv1: CIN=20, act0 [39,39,40] -> 18^3. Tile (6z,6y,18x), 648 threads,
// 1 z-output/thread. 6-deep cp.async ring; 2 ci per barrier phase.
// PDL: weight prologue pre-wait; gdc_wait before first act0 touch.
// ---------------------------------------------------------------------------
__global__ void __launch_bounds__(648, 1)
conv1_kernel(const float* __restrict__ in, const float* __restrict__ W,
             float* __restrict__ out, BC Bc)
{
    constexpr int SLAB = 600;
    extern __shared__ float dsm[];
    float* sW = dsm + 54000;                  // 1440, 16B-aligned
    float* sB = sW + 1440;                    // 30

    const int tid = threadIdx.x;
    const int b   = blockIdx.y;
    const int zt  = blockIdx.x / 3, yt = blockIdx.x % 3;
    const int oz0 = 6*zt, oy0 = 6*yt;

    for (int idx = tid; idx < 1440; idx += 648) {
        int ci = idx / 72, r = idx % 72, j = r / 24, o = r % 24;
        sW[idx] = (o < 23) ? W[(o*20 + ci)*3 + j] : 0.f;
    }
    if (tid < 30) sB[tid] = Bc.b[tid];

    const int ox  = tid % 18;
    const int r0  = tid / 18;
    const int oy  = r0 % 6;
    const int ozl = r0 / 6;        // 0..5

    float acc[24];
#pragma unroll
    for (int c = 0; c < 24; c++) acc[c] = 0.f;

    // fill: thread's slab/slot fixed across iterations (div/mod hoisted)
    const int f_iz0 = tid / 150;
    const int f_k0  = tid % 150;
    auto issue = [&](int ci) {
        float* dst = dsm + (ci % 6) * 9000;
        const float* g = in + (long)(b*20 + ci)*PLANE
                            + (2*oz0)*(PZ*PX) + (2*oy0)*PX;
        int iz = f_iz0, k = f_k0;
#pragma unroll
        for (int it = 0; it < 4; it++) {
            if (iz < 15)
                cp_async16(dst + iz*SLAB + 4*k, g + iz*(PZ*PX) + 4*k);
            iz += 4; k += 48;
            if (k >= 150) { k -= 150; iz += 1; }
        }
        asm volatile("cp.async.commit_group;");
    };

    auto compute = [&](int ci) {
        const float* cur = dsm + (ci % 6) * 9000;
        float T[10];
#pragma unroll
        for (int g = 0; g < 10; g++) T[g] = 0.f;
#pragma unroll
        for (int tz = 0; tz < 5; tz++) {
#pragma unroll
            for (int ty = 0; ty < 5; ty++) {
                const float2* rp = (const float2*)
                    &cur[(2*ozl + tz)*SLAB + (2*oy + ty)*PX + 2*ox];
                float2 c0 = rp[0], c1 = rp[1], c2 = rp[2];
                T[orbit_of(tz, ty, 0)] += c0.x;
                T[orbit_of(tz, ty, 1)] += c0.y;
                T[orbit_of(tz, ty, 2)] += c1.x;
                T[orbit_of(tz, ty, 3)] += c1.y;
                T[orbit_of(tz, ty, 4)] += c2.x;
            }
        }
        float U[3] = {};
#pragma unroll
        for (int j = 0; j < 3; j++)
#pragma unroll
        for (int g = 0; g < 10; g++)
            U[j] = fmaf(sB[j*10 + g], T[g], U[j]);
        const float4* w4 = (const float4*)&sW[ci*72];
#pragma unroll
        for (int j = 0; j < 3; j++)
#pragma unroll
        for (int q = 0; q < 6; q++) {
            float4 w = w4[j*6 + q];
            acc[q*4+0] = fmaf(U[j], w.x, acc[q*4+0]);
            acc[q*4+1] = fmaf(U[j], w.y, acc[q*4+1]);
            acc[q*4+2] = fmaf(U[j], w.z, acc[q*4+2]);
            acc[q*4+3] = fmaf(U[j], w.w, acc[q*4+3]);
        }
    };

    gdc_wait();                    // act0 ready (full conv0 grid complete)
    issue(0); issue(1); issue(2); issue(3);
    for (int cc = 0; cc < 10; cc++) {
        const int ci0 = 2*cc;
        if (cc < 9) { asm volatile("cp.async.wait_group 2;"); }
        else        { asm volatile("cp.async.wait_group 0;"); }
        __syncthreads();               // ci0, ci0+1 visible; fences prior
                                       // reads of bufs[(ci0+4)%6], [(ci0+5)%6]
        if (cc == 0) gdc_launch();     // all CTAs running -> let kS start
        if (cc < 9) { issue(ci0 + 4); issue(ci0 + 5); }
        compute(ci0);
        compute(ci0 + 1);
    }

    const int oz = oz0 + ozl;
    float* pb = out + (long)b * 20 * 5832
              + (long)oz*324 + (oy0 + oy)*18 + ox;      // channel stride 5832
    float g0 = fast_sigmoid(acc[20]);
    float g1 = fast_sigmoid(acc[21]);
    float g2 = fast_sigmoid(acc[22]);
#pragma unroll
    for (int oc = 0; oc < 20; oc++) {
        float y = acc[oc];
        float v = (oc < 5) ? fmaxf(y, 0.f)
                           : y * (oc < 8 ? g0 : (oc < 13 ? g1 : g2));
        pb[oc*5832] = v;
    }
}

// ---------------------------------------------------------------------------
// kS + fused B-contraction: V[b,ci,j] = sum_t B[j,orbit(t)] * S_t
// PDL: wait before act1 loads; trigger after.
// ---------------------------------------------------------------------------
__global__ void kS_kernel(const float* __restrict__ act, float* __restrict__ V,
                          BC Bc) {
    __shared__ float s[5832];
    __shared__ float R[1620];     // [z][y][tx]
    __shared__ float sS[128];
    int ci = blockIdx.x;
    int b  = blockIdx.y;
    int tid = threadIdx.x;        // 128
    gdc_wait();                   // act1 ready
    {   // vectorized tile load
        const float4* p4 = (const float4*)(act + (long)(b*20 + ci) * 5832);
        float4* s4 = (float4*)s;
        for (int i = tid; i < 1458; i += 128) s4[i] = p4[i];
    }
    __syncthreads();
    gdc_launch();

    for (int idx = tid; idx < 1620; idx += 128) {
        int z = idx / 90, r = idx % 90, y = r / 5, tx = r % 5;
        int lo = (3 - tx + 1) >> 1; if (lo < 0) lo = 0;
        int hi = (20 - tx) >> 1;    if (hi > 9) hi = 9;
        float sum = 0.f;
        const float* row = &s[(z*18 + y)*18];
        for (int oxx = lo; oxx <= hi; oxx++) sum += row[2*oxx + tx - 3];
        R[idx] = sum;
    }
    __syncthreads();

    if (tid < 125) {
        int tz = tid / 25, ty = (tid / 5) % 5, tx = tid % 5;
        int loz = (3 - tz + 1) >> 1; if (loz < 0) loz = 0;
        int hiz = (20 - tz) >> 1;    if (hiz > 9) hiz = 9;
        int loy = (3 - ty + 1) >> 1; if (loy < 0) loy = 0;
        int hiy = (20 - ty) >> 1;    if (hiy > 9) hiy = 9;
        float sum = 0.f;
        for (int oz = loz; oz <= hiz; oz++) {
            int z = 2*oz + tz - 3;
            for (int oyy = loy; oyy <= hiy; oyy++)
                sum += R[((z)*18 + (2*oyy + ty - 3))*5 + tx];
        }
        sS[tid] = sum;
    }
    __syncthreads();

    if (tid < 3) {
        float a = 0.f;
        for (int t = 0; t < 125; t++) {
            int tz = t / 25, ty = (t / 5) % 5, tx = t % 5;
            a = fmaf(Bc.b[tid*10 + orbit_of(tz, ty, tx)], sS[t], a);
        }
        V[(b*20 + ci)*3 + tid] = a;
    }
}

// ---------------------------------------------------------------------------
// head: one block per batch (16 x 128 thr). PDL: weights staged pre-wait.
// ---------------------------------------------------------------------------
__global__ void __launch_bounds__(128)
head_kernel(const float* __restrict__ V, const float* __restrict__ W2,
            const float* __restrict__ fc1w, const float* __restrict__ fc1b,
            const float* __restrict__ fc2w, const float* __restrict__ fc2b,
            float* __restrict__ out)
{
    __shared__ float sV[60];
    __shared__ float sW2[1380];
    __shared__ float sF1[1000];
    __shared__ float pooled[20];
    __shared__ float h1[52];
    const int b = blockIdx.x;
    const int t = threadIdx.x;     // 128
    {   // input-independent prologue: float4 weight staging
        const float4* w4 = (const float4*)W2;
        float4* d4 = (float4*)sW2;
        for (int i = t; i < 345; i += 128) d4[i] = w4[i];
        const float4* f4 = (const float4*)fc1w;
        float4* e4 = (float4*)sF1;
        for (int i = t; i < 250; i += 128) e4[i] = f4[i];
    }
    gdc_wait();                    // V ready
    if (t < 60) sV[t] = V[b*60 + t];
    __syncthreads();
    if (t < 20) {
        float a = 0.f;
        for (int k = 0; k < 60; k++)
            a = fmaf(sW2[t*60 + k], sV[k], a);
        pooled[t] = a * (1.0f/1000.0f);
    }
    __syncthreads();
    if (t < 50) {
        float a = fc1b[t];
        for (int k = 0; k < 20; k++)
            a = fmaf(pooled[k], sF1[t*20 + k], a);
        h1[t] = fmaxf(a, 0.f);
    }
    __syncthreads();
    if (t < 2) {
        float a = fc2b[t];
        for (int k = 0; k < 50; k++)
            a = fmaf(h1[k], fc2w[t*50 + k], a);
        out[b*2 + t] = a;
    }
}

// ---------------------------------------------------------------------------
extern "C" void kernel_launch(void* const* d_in, const int* in_sizes, int n_in,
                              void* d_out, int out_size) {
    const float* inp  = (const float*)d_in[0];
    const float* W0   = (const float*)d_in[1];
    const float* W1   = (const float*)d_in[2];
    const float* W2   = (const float*)d_in[3];
    const float* fc1w = (const float*)d_in[4];
    const float* fc1b = (const float*)d_in[5];
    const float* fc2w = (const float*)d_in[6];
    const float* fc2b = (const float*)d_in[7];
    float* out = (float*)d_out;

    BC bc;
    {
        const double r2s[10]  = {0,1,2,3,4,5,6,8,9,12};
        const double mult[10] = {1,6,12,8,6,24,24,12,24,8};
        for (int j = 0; j < 3; j++) {
            double v[10], sm = 0.0;
            for (int g = 0; g < 10; g++) {
                double d = (sqrt(r2s[g]) - (double)j) / 0.6;
                v[g] = exp(-0.5 * d * d);
                sm += mult[g] * v[g] * v[g];
            }
            double inv = 1.0 / sqrt(sm);
            for (int g = 0; g < 10; g++) bc.b[j*10 + g] = (float)(v[g] * inv);
        }
    }

    float *gA0, *gA1, *gV;
    cudaGetSymbolAddress((void**)&gA0, g_act0);
    cudaGetSymbolAddress((void**)&gA1, g_act1);
    cudaGetSymbolAddress((void**)&gV,  g_V);

    constexpr int SMEM0 = (13232 + 72 + 32) * 4;        // 53.3 KB
    cudaFuncSetAttribute(conv0_kernel,
                         cudaFuncAttributeMaxDynamicSharedMemorySize, SMEM0);
    conv0_kernel<<<dim3(4*11, 16), 297, SMEM0>>>(inp, W0, gA0, bc);

    cudaLaunchAttribute pdl[1];
    pdl[0].id = cudaLaunchAttributeProgrammaticStreamSerialization;
    pdl[0].val.programmaticStreamSerializationAllowed = 1;

    constexpr int SMEM1 = (54000 + 1440 + 32) * 4;      // 221.8 KB
    cudaFuncSetAttribute(conv1_kernel,
                         cudaFuncAttributeMaxDynamicSharedMemorySize, SMEM1);
    {
        cudaLaunchConfig_t cfg = {};
        cfg.gridDim = dim3(3*3, 16); cfg.blockDim = dim3(648);
        cfg.dynamicSmemBytes = SMEM1;
        cfg.attrs = pdl; cfg.numAttrs = 1;
        if (cudaLaunchKernelEx(&cfg, conv1_kernel, gA0, W1, gA1, bc)
            != cudaSuccess)
            conv1_kernel<<<dim3(3*3, 16), 648, SMEM1>>>(gA0, W1, gA1, bc);
    }
    {
        cudaLaunchConfig_t cfg = {};
        cfg.gridDim = dim3(20, 16); cfg.blockDim = dim3(128);
        cfg.dynamicSmemBytes = 0;
        cfg.attrs = pdl; cfg.numAttrs = 1;
        if (cudaLaunchKernelEx(&cfg, kS_kernel, (const float*)gA1, gV, bc)
            != cudaSuccess)
            kS_kernel<<<dim3(20, 16), 128>>>(gA1, gV, bc);
    }
    {
        cudaLaunchConfig_t cfg = {};
        cfg.gridDim = dim3(16); cfg.blockDim = dim3(128);
        cfg.dynamicSmemBytes = 0;
        cfg.attrs = pdl; cfg.numAttrs = 1;
        if (cudaLaunchKernelEx(&cfg, head_kernel, (const float*)gV, W2,
                               fc1w, fc1b, fc2w, fc2b, out) != cudaSuccess)
            head_kernel<<<16, 128>>>(gV, W2, fc1w, fc1b, fc2w, fc2b, out);
    }
}

// round 17
// speedup vs baseline: 1.2128x; 1.0517x over previous
#include <cuda_runtime.h>
#include <math.h>

// ---------------------------------------------------------------------------
// Factorized radial-basis CNN. R17 = R16 (best: 124.9us) with uniform-load
// offload: conv weights in __constant__ (LDCU path), basis read from kernel
// param; sW/sB smem staging deleted from conv0/conv1. All loops keep the
// same per-accumulator arithmetic order -> rel_err bit-identical.
// ---------------------------------------------------------------------------

#define PZ 39
#define PX 40
#define PLANE (PZ*PZ*PX)      // 60840 floats per (b,ci) act0 plane

__device__ float g_act0[16*20*PLANE];    // zero-init => halo+pad stay 0
__device__ float g_act1[16*20*18*18*18];
__device__ float g_V[16*20*3];

__constant__ float cW0[69];      // W0 [23][3]
__constant__ float cW1[1380];    // W1 [23][20][3]

struct BC { float b[30]; };   // [j*10 + orbit]

__host__ __device__ constexpr int orbit_of(int tz, int ty, int tx) {
    int dz = tz - 2, dy = ty - 2, dx = tx - 2;
    int r2 = dz*dz + dy*dy + dx*dx;            // {0..6, 8, 9, 12}
    return r2 <= 6 ? r2 : (r2 == 8 ? 7 : (r2 == 9 ? 8 : 9));
}

__device__ __forceinline__ void cp_async16(float* dst, const float* src) {
    unsigned int d = (unsigned int)__cvta_generic_to_shared(dst);
    asm volatile("cp.async.cg.shared.global [%0], [%1], 16;" :: "r"(d), "l"(src));
}

__device__ __forceinline__ float fast_sigmoid(float x) {
    return __fdividef(1.f, 1.f + __expf(-x));
}

__device__ __forceinline__ void gdc_wait()   { asm volatile("griddepcontrol.wait;" ::: "memory"); }
__device__ __forceinline__ void gdc_launch() { asm volatile("griddepcontrol.launch_dependents;"); }

// ---------------------------------------------------------------------------
// conv0: CIN=1, 64^3 -> 33^3 into padded [39,39,40]. Tile (9z,3y,33x),
// 297 threads; 3 CTAs/SM. Weights from __constant__, basis from param.
// ---------------------------------------------------------------------------
__global__ void __launch_bounds__(297, 3)
conv0_kernel(const float* __restrict__ in, float* __restrict__ out, BC Bc)
{
    extern __shared__ float sm0[];
    float* sIn = sm0;              // 21 z x 9 y x 70 x = 13230

    const int tid = threadIdx.x;
    const int b   = blockIdx.y;
    const int zt  = blockIdx.x / 11, yt = blockIdx.x % 11;
    const int oz0 = 9*zt, oy0 = 3*yt;

    // ---- tile load: 630 (iy,ix) pairs, each thread sweeps z for its pairs ----
    const float* gin = in + (long)b * (64*64*64);
    {
#pragma unroll
        for (int pr = 0; pr < 3; pr++) {
            int p = tid + 297*pr;
            if (p < 630) {
                int iy = p / 70, ix = p % 70;          // once per pair
                int gy = 2*oy0 - 3 + iy;
                int gx = ix - 3;
                bool yx_ok = (ix < 69) && ((unsigned)gy < 64u) && ((unsigned)gx < 64u);
                const float* gcol = gin + ((2*oz0 - 3)*64 + gy)*64 + gx;
                float* scol = sIn + iy*70 + ix;
#pragma unroll
                for (int iz = 0; iz < 21; iz++) {
                    int gz = 2*oz0 - 3 + iz;
                    float v = 0.f;
                    if (yx_ok && (unsigned)gz < 64u)
                        v = gcol[iz*4096];
                    scol[iz*630] = v;
                }
            }
        }
    }
    __syncthreads();
    gdc_launch();                  // let conv1 start its prologue

    const int ox = tid % 33;
    const int r0 = tid / 33;
    const int oy = r0 % 3;
    const int zg = r0 / 3;         // 0..2; thread's z-outputs: oz0+3*zg+p

    float T[3][10];
#pragma unroll
    for (int p = 0; p < 3; p++)
#pragma unroll
        for (int g = 0; g < 10; g++) T[p][g] = 0.f;

#pragma unroll
    for (int s = 0; s < 9; s++) {          // iz = 6*zg + s ; tz = s - 2p
#pragma unroll
        for (int ty = 0; ty < 5; ty++) {
            const float2* rp = (const float2*)
                &sIn[((6*zg + s)*9 + (2*oy + ty))*70 + 2*ox];
            float2 c0 = rp[0], c1 = rp[1], c2 = rp[2];
            float v0 = c0.x, v1 = c0.y, v2 = c1.x, v3 = c1.y, v4 = c2.x;
#pragma unroll
            for (int p = 0; p < 3; p++) {
                const int tz = s - 2*p;
                if (tz >= 0 && tz <= 4) {
                    T[p][orbit_of(tz, ty, 0)] += v0;
                    T[p][orbit_of(tz, ty, 1)] += v1;
                    T[p][orbit_of(tz, ty, 2)] += v2;
                    T[p][orbit_of(tz, ty, 3)] += v3;
                    T[p][orbit_of(tz, ty, 4)] += v4;
                }
            }
        }
    }

    float U[3][3] = {};
#pragma unroll
    for (int j = 0; j < 3; j++)
#pragma unroll
    for (int g = 0; g < 10; g++) {
        float bv = Bc.b[j*10 + g];
        U[0][j] = fmaf(bv, T[0][g], U[0][j]);
        U[1][j] = fmaf(bv, T[1][g], U[1][j]);
        U[2][j] = fmaf(bv, T[2][g], U[2][j]);
    }

    float* gout = out + (long)b * 20 * PLANE
                + (oy0 + oy + 3)*PX + (ox + 3);
#pragma unroll
    for (int p = 0; p < 3; p++) {
        const int oz = oz0 + 3*zg + p;
        if (oz > 32) continue;
        float y[23];
#pragma unroll
        for (int o = 0; o < 23; o++) {
            float a = 0.f;
#pragma unroll
            for (int j = 0; j < 3; j++)
                a = fmaf(U[p][j], cW0[o*3 + j], a);
            y[o] = a;
        }
        float g0 = fast_sigmoid(y[20]);
        float g1 = fast_sigmoid(y[21]);
        float g2 = fast_sigmoid(y[22]);
        float* pb = gout + (long)(oz + 3)*(PZ*PX);   // channel stride = PLANE
#pragma unroll
        for (int oc = 0; oc < 20; oc++) {
            float v = (oc < 5) ? fmaxf(y[oc], 0.f)
                               : y[oc] * (oc < 8 ? g0 : (oc < 13 ? g1 : g2));
            pb[oc*PLANE] = v;
        }
    }
}

// ---------------------------------------------------------------------------
// conv1: CIN=20, act0 [39,39,40] -> 18^3. Tile (6z,6y,18x), 648 threads,
// 1 z-output/thread. 6-deep cp.async ring; 2 ci per barrier phase; PDL.
// Weights from __constant__ (uniform LDCU), basis from param.
// ---------------------------------------------------------------------------
__global__ void __launch_bounds__(648, 1)
conv1_kernel(const float* __restrict__ in, float* __restrict__ out, BC Bc)
{
    constexpr int SLAB = 600;
    extern __shared__ float dsm[];     // 6 x 9000 floats

    const int tid = threadIdx.x;
    const int b   = blockIdx.y;
    const int zt  = blockIdx.x / 3, yt = blockIdx.x % 3;
    const int oz0 = 6*zt, oy0 = 6*yt;

    const int ox  = tid % 18;
    const int r0  = tid / 18;
    const int oy  = r0 % 6;
    const int ozl = r0 / 6;        // 0..5

    float acc[23];
#pragma unroll
    for (int c = 0; c < 23; c++) acc[c] = 0.f;

    // fill: thread's slab/slot fixed across iterations (div/mod hoisted)
    const int f_iz0 = tid / 150;
    const int f_k0  = tid % 150;
    auto issue = [&](int ci) {
        float* dst = dsm + (ci % 6) * 9000;
        const float* g = in + (long)(b*20 + ci)*PLANE
                            + (2*oz0)*(PZ*PX) + (2*oy0)*PX;
        int iz = f_iz0, k = f_k0;
#pragma unroll
        for (int it = 0; it < 4; it++) {
            if (iz < 15)
                cp_async16(dst + iz*SLAB + 4*k, g + iz*(PZ*PX) + 4*k);
            iz += 4; k += 48;
            if (k >= 150) { k -= 150; iz += 1; }
        }
        asm volatile("cp.async.commit_group;");
    };

    auto compute = [&](int ci) {
        const float* cur = dsm + (ci % 6) * 9000;
        float T[10];
#pragma unroll
        for (int g = 0; g < 10; g++) T[g] = 0.f;
#pragma unroll
        for (int tz = 0; tz < 5; tz++) {
#pragma unroll
            for (int ty = 0; ty < 5; ty++) {
                const float2* rp = (const float2*)
                    &cur[(2*ozl + tz)*SLAB + (2*oy + ty)*PX + 2*ox];
                float2 c0 = rp[0], c1 = rp[1], c2 = rp[2];
                T[orbit_of(tz, ty, 0)] += c0.x;
                T[orbit_of(tz, ty, 1)] += c0.y;
                T[orbit_of(tz, ty, 2)] += c1.x;
                T[orbit_of(tz, ty, 3)] += c1.y;
                T[orbit_of(tz, ty, 4)] += c2.x;
            }
        }
        float U[3] = {};
#pragma unroll
        for (int j = 0; j < 3; j++)
#pragma unroll
        for (int g = 0; g < 10; g++)
            U[j] = fmaf(Bc.b[j*10 + g], T[g], U[j]);
        const float* w = cW1 + ci*3;   // cW1[(o*20+ci)*3 + j] = w[o*60 + j]
#pragma unroll
        for (int o = 0; o < 23; o++) {
#pragma unroll
            for (int j = 0; j < 3; j++)
                acc[o] = fmaf(U[j], w[o*60 + j], acc[o]);
        }
    };

    gdc_wait();                    // act0 ready (full conv0 grid complete)
    issue(0); issue(1); issue(2); issue(3);
    for (int cc = 0; cc < 10; cc++) {
        const int ci0 = 2*cc;
        if (cc < 9) { asm volatile("cp.async.wait_group 2;"); }
        else        { asm volatile("cp.async.wait_group 0;"); }
        __syncthreads();               // ci0, ci0+1 visible; fences prior
                                       // reads of bufs[(ci0+4)%6], [(ci0+5)%6]
        if (cc == 0) gdc_launch();     // all CTAs running -> let kS start
        if (cc < 9) { issue(ci0 + 4); issue(ci0 + 5); }
        compute(ci0);
        compute(ci0 + 1);
    }

    const int oz = oz0 + ozl;
    float* pb = out + (long)b * 20 * 5832
              + (long)oz*324 + (oy0 + oy)*18 + ox;      // channel stride 5832
    float g0 = fast_sigmoid(acc[20]);
    float g1 = fast_sigmoid(acc[21]);
    float g2 = fast_sigmoid(acc[22]);
#pragma unroll
    for (int oc = 0; oc < 20; oc++) {
        float y = acc[oc];
        float v = (oc < 5) ? fmaxf(y, 0.f)
                           : y * (oc < 8 ? g0 : (oc < 13 ? g1 : g2));
        pb[oc*5832] = v;
    }
}

// ---------------------------------------------------------------------------
// kS + fused B-contraction: V[b,ci,j] = sum_t B[j,orbit(t)] * S_t  (R16 exact)
// ---------------------------------------------------------------------------
__global__ void kS_kernel(const float* __restrict__ act, float* __restrict__ V,
                          BC Bc) {
    __shared__ float s[5832];
    __shared__ float R[1620];     // [z][y][tx]
    __shared__ float sS[128];
    int ci = blockIdx.x;
    int b  = blockIdx.y;
    int tid = threadIdx.x;        // 128
    gdc_wait();                   // act1 ready
    {   // vectorized tile load
        const float4* p4 = (const float4*)(act + (long)(b*20 + ci) * 5832);
        float4* s4 = (float4*)s;
        for (int i = tid; i < 1458; i += 128) s4[i] = p4[i];
    }
    __syncthreads();
    gdc_launch();

    for (int idx = tid; idx < 1620; idx += 128) {
        int z = idx / 90, r = idx % 90, y = r / 5, tx = r % 5;
        int lo = (3 - tx + 1) >> 1; if (lo < 0) lo = 0;
        int hi = (20 - tx) >> 1;    if (hi > 9) hi = 9;
        float sum = 0.f;
        const float* row = &s[(z*18 + y)*18];
        for (int oxx = lo; oxx <= hi; oxx++) sum += row[2*oxx + tx - 3];
        R[idx] = sum;
    }
    __syncthreads();

    if (tid < 125) {
        int tz = tid / 25, ty = (tid / 5) % 5, tx = tid % 5;
        int loz = (3 - tz + 1) >> 1; if (loz < 0) loz = 0;
        int hiz = (20 - tz) >> 1;    if (hiz > 9) hiz = 9;
        int loy = (3 - ty + 1) >> 1; if (loy < 0) loy = 0;
        int hiy = (20 - ty) >> 1;    if (hiy > 9) hiy = 9;
        float sum = 0.f;
        for (int oz = loz; oz <= hiz; oz++) {
            int z = 2*oz + tz - 3;
            for (int oyy = loy; oyy <= hiy; oyy++)
                sum += R[((z)*18 + (2*oyy + ty - 3))*5 + tx];
        }
        sS[tid] = sum;
    }
    __syncthreads();

    if (tid < 3) {
        float a = 0.f;
        for (int t = 0; t < 125; t++) {
            int tz = t / 25, ty = (t / 5) % 5, tx = t % 5;
            a = fmaf(Bc.b[tid*10 + orbit_of(tz, ty, tx)], sS[t], a);
        }
        V[(b*20 + ci)*3 + tid] = a;
    }
}

// ---------------------------------------------------------------------------
// head: one block per batch (16 x 128 thr). PDL: weights staged pre-wait.
// (R16 exact)
// ---------------------------------------------------------------------------
__global__ void __launch_bounds__(128)
head_kernel(const float* __restrict__ V, const float* __restrict__ W2,
            const float* __restrict__ fc1w, const float* __restrict__ fc1b,
            const float* __restrict__ fc2w, const float* __restrict__ fc2b,
            float* __restrict__ out)
{
    __shared__ float sV[60];
    __shared__ float sW2[1380];
    __shared__ float sF1[1000];
    __shared__ float pooled[20];
    __shared__ float h1[52];
    const int b = blockIdx.x;
    const int t = threadIdx.x;     // 128
    {   // input-independent prologue: float4 weight staging
        const float4* w4 = (const float4*)W2;
        float4* d4 = (float4*)sW2;
        for (int i = t; i < 345; i += 128) d4[i] = w4[i];
        const float4* f4 = (const float4*)fc1w;
        float4* e4 = (float4*)sF1;
        for (int i = t; i < 250; i += 128) e4[i] = f4[i];
    }
    gdc_wait();                    // V ready
    if (t < 60) sV[t] = V[b*60 + t];
    __syncthreads();
    if (t < 20) {
        float a = 0.f;
        for (int k = 0; k < 60; k++)
            a = fmaf(sW2[t*60 + k], sV[k], a);
        pooled[t] = a * (1.0f/1000.0f);
    }
    __syncthreads();
    if (t < 50) {
        float a = fc1b[t];
        for (int k = 0; k < 20; k++)
            a = fmaf(pooled[k], sF1[t*20 + k], a);
        h1[t] = fmaxf(a, 0.f);
    }
    __syncthreads();
    if (t < 2) {
        float a = fc2b[t];
        for (int k = 0; k < 50; k++)
            a = fmaf(h1[k], fc2w[t*50 + k], a);
        out[b*2 + t] = a;
    }
}

// ---------------------------------------------------------------------------
extern "C" void kernel_launch(void* const* d_in, const int* in_sizes, int n_in,
                              void* d_out, int out_size) {
    const float* inp  = (const float*)d_in[0];
    const float* W0   = (const float*)d_in[1];
    const float* W1   = (const float*)d_in[2];
    const float* W2   = (const float*)d_in[3];
    const float* fc1w = (const float*)d_in[4];
    const float* fc1b = (const float*)d_in[5];
    const float* fc2w = (const float*)d_in[6];
    const float* fc2b = (const float*)d_in[7];
    float* out = (float*)d_out;

    BC bc;
    {
        const double r2s[10]  = {0,1,2,3,4,5,6,8,9,12};
        const double mult[10] = {1,6,12,8,6,24,24,12,24,8};
        for (int j = 0; j < 3; j++) {
            double v[10], sm = 0.0;
            for (int g = 0; g < 10; g++) {
                double d = (sqrt(r2s[g]) - (double)j) / 0.6;
                v[g] = exp(-0.5 * d * d);
                sm += mult[g] * v[g] * v[g];
            }
            double inv = 1.0 / sqrt(sm);
            for (int g = 0; g < 10; g++) bc.b[j*10 + g] = (float)(v[g] * inv);
        }
    }

    float *gA0, *gA1, *gV;
    cudaGetSymbolAddress((void**)&gA0, g_act0);
    cudaGetSymbolAddress((void**)&gA1, g_act1);
    cudaGetSymbolAddress((void**)&gV,  g_V);

    // weights into constant bank (D2D async copies; graph-capturable)
    cudaMemcpyToSymbolAsync(cW0, W0, 69*sizeof(float), 0,
                            cudaMemcpyDeviceToDevice);
    cudaMemcpyToSymbolAsync(cW1, W1, 1380*sizeof(float), 0,
                            cudaMemcpyDeviceToDevice);

    constexpr int SMEM0 = 13232 * 4;                    // 52.9 KB
    cudaFuncSetAttribute(conv0_kernel,
                         cudaFuncAttributeMaxDynamicSharedMemorySize, SMEM0);
    conv0_kernel<<<dim3(4*11, 16), 297, SMEM0>>>(inp, gA0, bc);

    cudaLaunchAttribute pdl[1];
    pdl[0].id = cudaLaunchAttributeProgrammaticStreamSerialization;
    pdl[0].val.programmaticStreamSerializationAllowed = 1;

    constexpr int SMEM1 = 54000 * 4;                    // 216 KB
    cudaFuncSetAttribute(conv1_kernel,
                         cudaFuncAttributeMaxDynamicSharedMemorySize, SMEM1);
    {
        cudaLaunchConfig_t cfg = {};
        cfg.gridDim = dim3(3*3, 16); cfg.blockDim = dim3(648);
        cfg.dynamicSmemBytes = SMEM1;
        cfg.attrs = pdl; cfg.numAttrs = 1;
        if (cudaLaunchKernelEx(&cfg, conv1_kernel, (const float*)gA0, gA1, bc)
            != cudaSuccess)
            conv1_kernel<<<dim3(3*3, 16), 648, SMEM1>>>(gA0, gA1, bc);
    }
    {
        cudaLaunchConfig_t cfg = {};
        cfg.gridDim = dim3(20, 16); cfg.blockDim = dim3(128);
        cfg.dynamicSmemBytes = 0;
        cfg.attrs = pdl; cfg.numAttrs = 1;
        if (cudaLaunchKernelEx(&cfg, kS_kernel, (const float*)gA1, gV, bc)
            != cudaSuccess)
            kS_kernel<<<dim3(20, 16), 128>>>(gA1, gV, bc);
    }
    {
        cudaLaunchConfig_t cfg = {};
        cfg.gridDim = dim3(16); cfg.blockDim = dim3(128);
        cfg.dynamicSmemBytes = 0;
        cfg.attrs = pdl; cfg.numAttrs = 1;
        if (cudaLaunchKernelEx(&cfg, head_kernel, (const float*)gV, W2,
                               fc1w, fc1b, fc2w, fc2b, out) != cudaSuccess)
            head_kernel<<<16, 128>>>(gV, W2, fc1w, fc1b, fc2w, fc2b, out);
    }
}